// round 3
// baseline (speedup 1.0000x reference)
#include <cuda_runtime.h>
#include <cuda_bf16.h>
#include <math.h>

#define Bz 32
#define Tz 128
#define Ez 512
#define Hz 1024
#define Gz 4096   // 4*H
#define Vz 32000
#define TB 4096   // T*B

// ---------------- scratch (static device globals; no allocs allowed) ----------
__device__ float g_xg[(size_t)TB * Gz];     // 64 MB: precomputed input gates
__device__ float g_bufA[(size_t)TB * Hz];   // 16 MB
__device__ float g_bufB[(size_t)TB * Hz];   // 16 MB
__device__ float g_WT[(size_t)Hz * Gz];     // 16 MB: transposed Whh
__device__ float g_c[Bz * Hz];
__device__ float g_hf0[Bz * Hz];
__device__ float g_cf0[Bz * Hz];
__device__ float g_hf1[Bz * Hz];
__device__ float g_cf1[Bz * Hz];
__device__ float g_zero[Bz * Hz];

// ---------------- small helpers ----------------------------------------------
__global__ void zero_k(float* p, int n) {
    int i = blockIdx.x * blockDim.x + threadIdx.x;
    if (i < n) p[i] = 0.f;
}
__global__ void copy_k(float* d, const float* s, int n) {
    int i = blockIdx.x * blockDim.x + threadIdx.x;
    if (i < n) d[i] = s[i];
}

// ---------------- embedding gathers ([T,B,E] time-major) ---------------------
__global__ void embed_enc(const int* __restrict__ x, const float* __restrict__ emb,
                          float* __restrict__ out) {
    int tb = blockIdx.x;            // t*B + b
    int t = tb >> 5, b = tb & 31;
    int tok = x[b * Tz + t];
    const float4* src = (const float4*)(emb + (size_t)tok * Ez);
    float4* dst = (float4*)(out + (size_t)tb * Ez);
    dst[threadIdx.x] = src[threadIdx.x];    // 128 threads * float4 = 512 floats
}

__global__ void embed_dec(const int* __restrict__ tgt, const float* __restrict__ emb,
                          float* __restrict__ out) {
    int tb = blockIdx.x;
    int t = tb >> 5, b = tb & 31;
    int tok = (t == 0) ? 0 : tgt[b * Tz + t - 1];
    const float4* src = (const float4*)(emb + (size_t)tok * Ez);
    float4* dst = (float4*)(out + (size_t)tb * Ez);
    dst[threadIdx.x] = src[threadIdx.x];
}

// ---------------- Whh transpose: W[4096][1024] -> WT[1024][4096] --------------
__global__ void transpose_wh(const float* __restrict__ W, float* __restrict__ WT) {
    __shared__ float tile[32][33];
    int n0 = blockIdx.x * 32;   // over N=4096
    int k0 = blockIdx.y * 32;   // over K=1024
    int tx = threadIdx.x, ty = threadIdx.y;
#pragma unroll
    for (int r = 0; r < 32; r += 8)
        tile[ty + r][tx] = W[(size_t)(n0 + ty + r) * Hz + k0 + tx];
    __syncthreads();
#pragma unroll
    for (int r = 0; r < 32; r += 8)
        WT[(size_t)(k0 + ty + r) * Gz + n0 + tx] = tile[tx][ty + r];
}

// ---------------- tiled SGEMM: C[M,N] = A[M,K] @ W[N,K]^T + bias[N] -----------
// REMAP==0: C row-major [M,N].  REMAP==1: FC output remap m=(t*32+b) -> out[b][t][n].
template <int REMAP>
__global__ __launch_bounds__(256, 2)
void sgemm(const float* __restrict__ A, const float* __restrict__ W,
           const float* __restrict__ bias, float* __restrict__ C,
           int M, int N, int K) {
    __shared__ float As[16][132];
    __shared__ float Bs[16][132];

    int tid = threadIdx.x;
    int tx = tid & 15;          // col group
    int ty = tid >> 4;          // row group
    int m0 = blockIdx.y * 128;
    int n0 = blockIdx.x * 128;

    float acc[8][8];
#pragma unroll
    for (int i = 0; i < 8; i++)
#pragma unroll
        for (int j = 0; j < 8; j++) acc[i][j] = 0.f;

    int r = tid >> 2;           // 0..63
    int q = tid & 3;            // 0..3 (k-quad)

    for (int k0 = 0; k0 < K; k0 += 16) {
        // load A tile (128x16), store transposed As[k][m]
#pragma unroll
        for (int s = 0; s < 2; s++) {
            int m = m0 + r + s * 64;
            float4 v = *(const float4*)(A + (size_t)m * K + k0 + q * 4);
            As[q * 4 + 0][r + s * 64] = v.x;
            As[q * 4 + 1][r + s * 64] = v.y;
            As[q * 4 + 2][r + s * 64] = v.z;
            As[q * 4 + 3][r + s * 64] = v.w;
        }
        // load W tile (128 rows of N x 16 of K), store Bs[k][n]
#pragma unroll
        for (int s = 0; s < 2; s++) {
            int n = n0 + r + s * 64;
            float4 v = *(const float4*)(W + (size_t)n * K + k0 + q * 4);
            Bs[q * 4 + 0][r + s * 64] = v.x;
            Bs[q * 4 + 1][r + s * 64] = v.y;
            Bs[q * 4 + 2][r + s * 64] = v.z;
            Bs[q * 4 + 3][r + s * 64] = v.w;
        }
        __syncthreads();
#pragma unroll
        for (int k = 0; k < 16; k++) {
            float a[8], b[8];
            *(float4*)&a[0] = *(const float4*)&As[k][ty * 8];
            *(float4*)&a[4] = *(const float4*)&As[k][ty * 8 + 4];
            *(float4*)&b[0] = *(const float4*)&Bs[k][tx * 8];
            *(float4*)&b[4] = *(const float4*)&Bs[k][tx * 8 + 4];
#pragma unroll
            for (int i = 0; i < 8; i++)
#pragma unroll
                for (int j = 0; j < 8; j++) acc[i][j] += a[i] * b[j];
        }
        __syncthreads();
    }

#pragma unroll
    for (int i = 0; i < 8; i++) {
        int m = m0 + ty * 8 + i;
#pragma unroll
        for (int j = 0; j < 8; j++) {
            int n = n0 + tx * 8 + j;
            float v = acc[i][j] + bias[n];
            if (REMAP) {
                int b = m & 31, t = m >> 5;
                C[((size_t)b * Tz + t) * Vz + n] = v;
            } else {
                C[(size_t)m * N + n] = v;
            }
        }
    }
}

// ---------------- fused LSTM step: gates = xg[t] + h_prev @ Whh^T; cell -------
// grid 128 CTAs (8 h-cols each), 128 threads.
__device__ __forceinline__ float sigm(float x) { return 1.f / (1.f + expf(-x)); }

__global__ __launch_bounds__(128)
void lstm_step(int t, const float* __restrict__ xg, const float* __restrict__ WT,
               const float* __restrict__ h0, float* __restrict__ hseq,
               float* __restrict__ c) {
    const float* hprev = (t == 0) ? h0 : (hseq + (size_t)(t - 1) * Bz * Hz);

    __shared__ float h_s[64][32];     // [k-chunk][batch]
    __shared__ float Ws[64][32];      // [k-chunk][gate-col]
    __shared__ float gs[4][32][8];    // [gate][batch][h-col]

    int tid = threadIdx.x;
    int ni = tid & 31;                // gate-col within CTA (0..31)
    int bi = tid >> 5;                // batch group (0..3), 8 batches each
    int g = ni >> 3, jj = ni & 7;
    int j0 = blockIdx.x * 8;          // h-col base
    int gcol = g * Hz + j0 + jj;      // global gate column

    float acc[8];
#pragma unroll
    for (int u = 0; u < 8; u++) acc[u] = 0.f;

    for (int kc = 0; kc < Hz; kc += 64) {
        // stage h chunk transposed: h_s[kk][b] = hprev[b*Hz + kc + kk]
        {
            int b = tid >> 2;         // 0..31
            int kq = tid & 3;         // 0..3
            const float4* src = (const float4*)(hprev + (size_t)b * Hz + kc);
#pragma unroll
            for (int u = 0; u < 4; u++) {
                float4 v = src[kq * 4 + u];
                int kk = (kq * 4 + u) * 4;
                h_s[kk + 0][b] = v.x; h_s[kk + 1][b] = v.y;
                h_s[kk + 2][b] = v.z; h_s[kk + 3][b] = v.w;
            }
        }
        // stage W chunk: Ws[kk][cc] = WT[(kc+kk)*Gz + colmap(cc)]
#pragma unroll
        for (int u = 0; u < 16; u++) {
            int i = tid + 128 * u;
            int kk = i >> 5, cc = i & 31;
            int gc = (cc >> 3) * Hz + j0 + (cc & 7);
            Ws[kk][cc] = WT[(size_t)(kc + kk) * Gz + gc];
        }
        __syncthreads();
#pragma unroll
        for (int kk = 0; kk < 64; kk++) {
            float w = Ws[kk][ni];
            const float* hr = &h_s[kk][bi * 8];
            float4 hA = *(const float4*)hr;
            float4 hB = *(const float4*)(hr + 4);
            acc[0] += hA.x * w; acc[1] += hA.y * w;
            acc[2] += hA.z * w; acc[3] += hA.w * w;
            acc[4] += hB.x * w; acc[5] += hB.y * w;
            acc[6] += hB.z * w; acc[7] += hB.w * w;
        }
        __syncthreads();
    }

    // add precomputed input gates, stash for cell compute
#pragma unroll
    for (int u = 0; u < 8; u++) {
        int b = bi * 8 + u;
        gs[g][b][jj] = acc[u] + xg[((size_t)t * Bz + b) * Gz + gcol];
    }
    __syncthreads();

    // LSTM cell: 32 batches x 8 h-cols, 2 elements per thread
#pragma unroll
    for (int u = 0; u < 2; u++) {
        int e = tid + 128 * u;
        int b = e >> 3, j = e & 7;
        float iv = gs[0][b][j];
        float fv = gs[1][b][j];
        float gv = gs[2][b][j];
        float ov = gs[3][b][j];
        int idx = b * Hz + j0 + j;
        float cprev = c[idx];
        float cn = sigm(fv) * cprev + sigm(iv) * tanhf(gv);
        c[idx] = cn;
        hseq[(size_t)t * Bz * Hz + idx] = sigm(ov) * tanhf(cn);
    }
}

// ---------------- in-place log_softmax over rows of length V ------------------
__global__ __launch_bounds__(256)
void logsoftmax_k(float* __restrict__ out) {
    float* row = out + (size_t)blockIdx.x * Vz;
    float4* r4 = (float4*)row;
    const int tid = threadIdx.x;
    __shared__ float sred[32];

    float m = -1e30f;
    for (int i = tid; i < Vz / 4; i += 256) {
        float4 v = r4[i];
        m = fmaxf(m, fmaxf(fmaxf(v.x, v.y), fmaxf(v.z, v.w)));
    }
#pragma unroll
    for (int o = 16; o; o >>= 1) m = fmaxf(m, __shfl_xor_sync(~0u, m, o));
    if ((tid & 31) == 0) sred[tid >> 5] = m;
    __syncthreads();
    {
        float t = (tid < 8) ? sred[tid] : -1e30f;
#pragma unroll
        for (int o = 16; o; o >>= 1) t = fmaxf(t, __shfl_xor_sync(~0u, t, o));
        if (tid == 0) sred[0] = t;
    }
    __syncthreads();
    float M = sred[0];
    __syncthreads();

    float s = 0.f;
    for (int i = tid; i < Vz / 4; i += 256) {
        float4 v = r4[i];
        s += __expf(v.x - M) + __expf(v.y - M) + __expf(v.z - M) + __expf(v.w - M);
    }
#pragma unroll
    for (int o = 16; o; o >>= 1) s += __shfl_xor_sync(~0u, s, o);
    if ((tid & 31) == 0) sred[tid >> 5] = s;
    __syncthreads();
    {
        float t = (tid < 8) ? sred[tid] : 0.f;
#pragma unroll
        for (int o = 16; o; o >>= 1) t += __shfl_xor_sync(~0u, t, o);
        if (tid == 0) sred[0] = t;
    }
    __syncthreads();
    float lse = M + logf(sred[0]);

    for (int i = tid; i < Vz / 4; i += 256) {
        float4 v = r4[i];
        v.x -= lse; v.y -= lse; v.z -= lse; v.w -= lse;
        r4[i] = v;
    }
}

// ---------------- driver ------------------------------------------------------
extern "C" void kernel_launch(void* const* d_in, const int* in_sizes, int n_in,
                              void* d_out, int out_size) {
    const int*   x     = (const int*)d_in[0];
    const int*   tgt   = (const int*)d_in[1];
    const float* emb   = (const float*)d_in[2];
    const float* eWih0 = (const float*)d_in[3];
    const float* eWhh0 = (const float*)d_in[4];
    const float* eb0   = (const float*)d_in[5];
    const float* eWih1 = (const float*)d_in[6];
    const float* eWhh1 = (const float*)d_in[7];
    const float* eb1   = (const float*)d_in[8];
    const float* dWih0 = (const float*)d_in[9];
    const float* dWhh0 = (const float*)d_in[10];
    const float* db0   = (const float*)d_in[11];
    const float* dWih1 = (const float*)d_in[12];
    const float* dWhh1 = (const float*)d_in[13];
    const float* db1   = (const float*)d_in[14];
    const float* fcW   = (const float*)d_in[15];
    const float* fcb   = (const float*)d_in[16];
    float* out = (float*)d_out;

    float *xg, *bufA, *bufB, *WT, *c, *hf0, *cf0, *hf1, *cf1, *zr;
    cudaGetSymbolAddress((void**)&xg,   g_xg);
    cudaGetSymbolAddress((void**)&bufA, g_bufA);
    cudaGetSymbolAddress((void**)&bufB, g_bufB);
    cudaGetSymbolAddress((void**)&WT,   g_WT);
    cudaGetSymbolAddress((void**)&c,    g_c);
    cudaGetSymbolAddress((void**)&hf0,  g_hf0);
    cudaGetSymbolAddress((void**)&cf0,  g_cf0);
    cudaGetSymbolAddress((void**)&hf1,  g_hf1);
    cudaGetSymbolAddress((void**)&cf1,  g_cf1);
    cudaGetSymbolAddress((void**)&zr,   g_zero);

    const int BH = Bz * Hz;
    dim3 gGate(Gz / 128, TB / 128);       // (32, 32)
    dim3 gFC(Vz / 128, TB / 128);         // (250, 32)
    dim3 gT(128, 32), bT(32, 8);

    // ---------- encoder layer 0 ----------
    embed_enc<<<TB, 128>>>(x, emb, bufA);
    sgemm<0><<<gGate, 256>>>(bufA, eWih0, eb0, xg, TB, Gz, Ez);
    transpose_wh<<<gT, bT>>>(eWhh0, WT);
    zero_k<<<BH / 256, 256>>>(zr, BH);
    zero_k<<<BH / 256, 256>>>(c, BH);
    for (int t = 0; t < Tz; t++) lstm_step<<<128, 128>>>(t, xg, WT, zr, bufB, c);
    copy_k<<<BH / 256, 256>>>(hf0, bufB + (size_t)(Tz - 1) * BH, BH);
    copy_k<<<BH / 256, 256>>>(cf0, c, BH);

    // ---------- encoder layer 1 ----------
    sgemm<0><<<gGate, 256>>>(bufB, eWih1, eb1, xg, TB, Gz, Hz);
    transpose_wh<<<gT, bT>>>(eWhh1, WT);
    zero_k<<<BH / 256, 256>>>(c, BH);
    for (int t = 0; t < Tz; t++) lstm_step<<<128, 128>>>(t, xg, WT, zr, bufA, c);
    copy_k<<<BH / 256, 256>>>(hf1, bufA + (size_t)(Tz - 1) * BH, BH);
    copy_k<<<BH / 256, 256>>>(cf1, c, BH);

    // ---------- decoder layer 0 (init = enc layer0 finals) ----------
    embed_dec<<<TB, 128>>>(tgt, emb, bufB);
    sgemm<0><<<gGate, 256>>>(bufB, dWih0, db0, xg, TB, Gz, Ez);
    transpose_wh<<<gT, bT>>>(dWhh0, WT);
    for (int t = 0; t < Tz; t++) lstm_step<<<128, 128>>>(t, xg, WT, hf0, bufA, cf0);

    // ---------- decoder layer 1 (init = enc layer1 finals) ----------
    sgemm<0><<<gGate, 256>>>(bufA, dWih1, db1, xg, TB, Gz, Hz);
    transpose_wh<<<gT, bT>>>(dWhh1, WT);
    for (int t = 0; t < Tz; t++) lstm_step<<<128, 128>>>(t, xg, WT, hf1, bufB, cf1);

    // ---------- FC projection (fused b,t remap) + log_softmax ----------
    sgemm<1><<<gFC, 256>>>(bufB, fcW, fcb, out, TB, Vz, Hz);
    logsoftmax_k<<<TB, 256>>>(out);
}

// round 5
// speedup vs baseline: 1.3180x; 1.3180x over previous
#include <cuda_runtime.h>
#include <cuda_bf16.h>
#include <math.h>
#include <stdint.h>

#define Bz 32
#define Tz 128
#define Ez 512
#define Hz 1024
#define Gz 4096   // 4*H
#define Vz 32000
#define TB 4096   // T*B
#define PITCH 40  // smem row pitch (bf16 elems) for conflict-free ldmatrix

// ---------------- scratch (static device globals; no allocs allowed) ----------
__device__ float g_xg[(size_t)TB * Gz];            // 64 MB: precomputed input gates
__device__ float g_bufA[(size_t)TB * Hz];          // 16 MB
__device__ float g_bufB[(size_t)TB * Hz];          // 16 MB
__device__ float g_WT[(size_t)Hz * Gz];            // 16 MB: transposed Whh
__device__ __nv_bfloat16 g_Abf[(size_t)TB * Hz];   // 8 MB: bf16 activations
__device__ __nv_bfloat16 g_Wbf[(size_t)Vz * Hz];   // 64 MB: bf16 weights (max fcW)
__device__ float g_c[Bz * Hz];
__device__ float g_hf0[Bz * Hz];
__device__ float g_cf0[Bz * Hz];
__device__ float g_hf1[Bz * Hz];
__device__ float g_cf1[Bz * Hz];
__device__ float g_zero[Bz * Hz];

// ---------------- small helpers ----------------------------------------------
__global__ void zero_k(float* p, int n) {
    int i = blockIdx.x * blockDim.x + threadIdx.x;
    if (i < n) p[i] = 0.f;
}
__global__ void copy_k(float* d, const float* s, int n) {
    int i = blockIdx.x * blockDim.x + threadIdx.x;
    if (i < n) d[i] = s[i];
}
// fp32 -> bf16, 4 elems/thread (n % 4 == 0 always here)
__global__ void f2bf(__nv_bfloat16* __restrict__ d, const float* __restrict__ s, int n) {
    int i = (blockIdx.x * blockDim.x + threadIdx.x) * 4;
    if (i < n) {
        float4 v = *(const float4*)(s + i);
        __nv_bfloat162 lo = __floats2bfloat162_rn(v.x, v.y);
        __nv_bfloat162 hi = __floats2bfloat162_rn(v.z, v.w);
        uint2 pk;
        pk.x = *(uint32_t*)&lo;
        pk.y = *(uint32_t*)&hi;
        *(uint2*)(d + i) = pk;
    }
}

__device__ __forceinline__ uint32_t s2u(const void* p) {
    return (uint32_t)__cvta_generic_to_shared(p);
}

// ---------------- embedding gathers ([T,B,E] time-major) ---------------------
__global__ void embed_enc(const int* __restrict__ x, const float* __restrict__ emb,
                          float* __restrict__ out) {
    int tb = blockIdx.x;            // t*B + b
    int t = tb >> 5, b = tb & 31;
    int tok = x[b * Tz + t];
    const float4* src = (const float4*)(emb + (size_t)tok * Ez);
    float4* dst = (float4*)(out + (size_t)tb * Ez);
    dst[threadIdx.x] = src[threadIdx.x];
}

__global__ void embed_dec(const int* __restrict__ tgt, const float* __restrict__ emb,
                          float* __restrict__ out) {
    int tb = blockIdx.x;
    int t = tb >> 5, b = tb & 31;
    int tok = (t == 0) ? 0 : tgt[b * Tz + t - 1];
    const float4* src = (const float4*)(emb + (size_t)tok * Ez);
    float4* dst = (float4*)(out + (size_t)tb * Ez);
    dst[threadIdx.x] = src[threadIdx.x];
}

// ---------------- Whh transpose: W[4096][1024] -> WT[1024][4096] --------------
__global__ void transpose_wh(const float* __restrict__ W, float* __restrict__ WT) {
    __shared__ float tile[32][33];
    int n0 = blockIdx.x * 32;
    int k0 = blockIdx.y * 32;
    int tx = threadIdx.x, ty = threadIdx.y;
#pragma unroll
    for (int r = 0; r < 32; r += 8)
        tile[ty + r][tx] = W[(size_t)(n0 + ty + r) * Hz + k0 + tx];
    __syncthreads();
#pragma unroll
    for (int r = 0; r < 32; r += 8)
        WT[(size_t)(k0 + ty + r) * Gz + n0 + tx] = tile[tx][ty + r];
}

// ---------------- bf16 tensor-core GEMM: C = A[M,K] @ W[N,K]^T + bias ---------
// CTA tile 128x128, BK=32, 8 warps (2x4), warp tile 64x32, mma m16n8k16 bf16.
// REMAP==1: FC epilogue remap m=(t*32+b) -> out[b][t][n].
template <int REMAP>
__global__ __launch_bounds__(256)
void bgemm(const __nv_bfloat16* __restrict__ A, const __nv_bfloat16* __restrict__ W,
           const float* __restrict__ bias, float* __restrict__ C,
           int M, int N, int K) {
    __shared__ __nv_bfloat16 As[128 * PITCH];
    __shared__ __nv_bfloat16 Ws[128 * PITCH];

    int tid = threadIdx.x;
    int wid = tid >> 5, lane = tid & 31;
    int wm = wid >> 2;            // 0..1  (64-row slab)
    int wn = wid & 3;             // 0..3  (32-col slab)
    int m0 = blockIdx.y * 128;
    int n0 = blockIdx.x * 128;

    float acc[4][4][4];
#pragma unroll
    for (int a = 0; a < 4; a++)
#pragma unroll
        for (int b = 0; b < 4; b++)
#pragma unroll
            for (int cidx = 0; cidx < 4; cidx++) acc[a][b][cidx] = 0.f;

    for (int k0 = 0; k0 < K; k0 += 32) {
        // stage A tile (128x32) and W tile (128x32): 512 16B chunks each
#pragma unroll
        for (int s = 0; s < 2; s++) {
            int c = tid + s * 256;
            int row = c >> 2, seg = c & 3;
            uint4 va = *(const uint4*)(A + (size_t)(m0 + row) * K + k0 + seg * 8);
            *(uint4*)(As + row * PITCH + seg * 8) = va;
            uint4 vw = *(const uint4*)(W + (size_t)(n0 + row) * K + k0 + seg * 8);
            *(uint4*)(Ws + row * PITCH + seg * 8) = vw;
        }
        __syncthreads();

#pragma unroll
        for (int ks = 0; ks < 32; ks += 16) {
            uint32_t afr[4][4];
            uint32_t bfr[4][2];
            // A fragments via ldmatrix x4 (16x16 bf16 tiles)
#pragma unroll
            for (int mt = 0; mt < 4; mt++) {
                int row = wm * 64 + mt * 16 + (lane & 15);
                int col = ks + ((lane >> 4) << 3);
                uint32_t addr = s2u(As + row * PITCH + col);
                asm volatile(
                    "ldmatrix.sync.aligned.m8n8.x4.shared.b16 {%0,%1,%2,%3},[%4];"
                    : "=r"(afr[mt][0]), "=r"(afr[mt][1]), "=r"(afr[mt][2]), "=r"(afr[mt][3])
                    : "r"(addr));
            }
            // B fragments via ldmatrix x2 ([n][k] layout, non-trans)
#pragma unroll
            for (int nt = 0; nt < 4; nt++) {
                int row = wn * 32 + nt * 8 + (lane & 7);
                int col = ks + (((lane >> 3) & 1) << 3);
                uint32_t addr = s2u(Ws + row * PITCH + col);
                asm volatile(
                    "ldmatrix.sync.aligned.m8n8.x2.shared.b16 {%0,%1},[%2];"
                    : "=r"(bfr[nt][0]), "=r"(bfr[nt][1])
                    : "r"(addr));
            }
#pragma unroll
            for (int mt = 0; mt < 4; mt++)
#pragma unroll
                for (int nt = 0; nt < 4; nt++) {
                    asm volatile(
                        "mma.sync.aligned.m16n8k16.row.col.f32.bf16.bf16.f32 "
                        "{%0,%1,%2,%3},{%4,%5,%6,%7},{%8,%9},{%0,%1,%2,%3};"
                        : "+f"(acc[mt][nt][0]), "+f"(acc[mt][nt][1]),
                          "+f"(acc[mt][nt][2]), "+f"(acc[mt][nt][3])
                        : "r"(afr[mt][0]), "r"(afr[mt][1]), "r"(afr[mt][2]), "r"(afr[mt][3]),
                          "r"(bfr[nt][0]), "r"(bfr[nt][1]));
                }
        }
        __syncthreads();
    }

    // epilogue: c0,c1 -> (row, col..col+1); c2,c3 -> (row+8, ...)
#pragma unroll
    for (int mt = 0; mt < 4; mt++) {
#pragma unroll
        for (int nt = 0; nt < 4; nt++) {
            int col = n0 + wn * 32 + nt * 8 + (lane & 3) * 2;
            float b0 = bias[col], b1 = bias[col + 1];
#pragma unroll
            for (int half = 0; half < 2; half++) {
                int m = m0 + wm * 64 + mt * 16 + (lane >> 2) + half * 8;
                float2 v;
                v.x = acc[mt][nt][half * 2 + 0] + b0;
                v.y = acc[mt][nt][half * 2 + 1] + b1;
                if (REMAP) {
                    int b = m & 31, t = m >> 5;
                    *(float2*)(C + ((size_t)b * Tz + t) * Vz + col) = v;
                } else {
                    *(float2*)(C + (size_t)m * N + col) = v;
                }
            }
        }
    }
}

// ---------------- fused LSTM step (fp32 recurrence) ---------------------------
__device__ __forceinline__ float sigm(float x) { return 1.f / (1.f + expf(-x)); }

__global__ __launch_bounds__(128)
void lstm_step(int t, const float* __restrict__ xg, const float* __restrict__ WT,
               const float* __restrict__ h0, float* __restrict__ hseq,
               float* __restrict__ c) {
    const float* hprev = (t == 0) ? h0 : (hseq + (size_t)(t - 1) * Bz * Hz);

    __shared__ float h_s[64][32];
    __shared__ float Ws[64][32];
    __shared__ float gs[4][32][8];

    int tid = threadIdx.x;
    int ni = tid & 31;
    int bi = tid >> 5;
    int g = ni >> 3, jj = ni & 7;
    int j0 = blockIdx.x * 8;
    int gcol = g * Hz + j0 + jj;

    float acc[8];
#pragma unroll
    for (int u = 0; u < 8; u++) acc[u] = 0.f;

    for (int kc = 0; kc < Hz; kc += 64) {
        {
            int b = tid >> 2;
            int kq = tid & 3;
            const float4* src = (const float4*)(hprev + (size_t)b * Hz + kc);
#pragma unroll
            for (int u = 0; u < 4; u++) {
                float4 v = src[kq * 4 + u];
                int kk = (kq * 4 + u) * 4;
                h_s[kk + 0][b] = v.x; h_s[kk + 1][b] = v.y;
                h_s[kk + 2][b] = v.z; h_s[kk + 3][b] = v.w;
            }
        }
#pragma unroll
        for (int u = 0; u < 16; u++) {
            int i = tid + 128 * u;
            int kk = i >> 5, cc = i & 31;
            int gc = (cc >> 3) * Hz + j0 + (cc & 7);
            Ws[kk][cc] = WT[(size_t)(kc + kk) * Gz + gc];
        }
        __syncthreads();
#pragma unroll
        for (int kk = 0; kk < 64; kk++) {
            float w = Ws[kk][ni];
            const float* hr = &h_s[kk][bi * 8];
            float4 hA = *(const float4*)hr;
            float4 hB = *(const float4*)(hr + 4);
            acc[0] += hA.x * w; acc[1] += hA.y * w;
            acc[2] += hA.z * w; acc[3] += hA.w * w;
            acc[4] += hB.x * w; acc[5] += hB.y * w;
            acc[6] += hB.z * w; acc[7] += hB.w * w;
        }
        __syncthreads();
    }

#pragma unroll
    for (int u = 0; u < 8; u++) {
        int b = bi * 8 + u;
        gs[g][b][jj] = acc[u] + xg[((size_t)t * Bz + b) * Gz + gcol];
    }
    __syncthreads();

#pragma unroll
    for (int u = 0; u < 2; u++) {
        int e = tid + 128 * u;
        int b = e >> 3, j = e & 7;
        float iv = gs[0][b][j];
        float fv = gs[1][b][j];
        float gv = gs[2][b][j];
        float ov = gs[3][b][j];
        int idx = b * Hz + j0 + j;
        float cprev = c[idx];
        float cn = sigm(fv) * cprev + sigm(iv) * tanhf(gv);
        c[idx] = cn;
        hseq[(size_t)t * Bz * Hz + idx] = sigm(ov) * tanhf(cn);
    }
}

// ---------------- in-place log_softmax over rows of length V ------------------
__global__ __launch_bounds__(256)
void logsoftmax_k(float* __restrict__ out) {
    float* row = out + (size_t)blockIdx.x * Vz;
    float4* r4 = (float4*)row;
    const int tid = threadIdx.x;
    __shared__ float sred[32];

    float m = -1e30f;
    for (int i = tid; i < Vz / 4; i += 256) {
        float4 v = r4[i];
        m = fmaxf(m, fmaxf(fmaxf(v.x, v.y), fmaxf(v.z, v.w)));
    }
#pragma unroll
    for (int o = 16; o; o >>= 1) m = fmaxf(m, __shfl_xor_sync(~0u, m, o));
    if ((tid & 31) == 0) sred[tid >> 5] = m;
    __syncthreads();
    {
        float t = (tid < 8) ? sred[tid] : -1e30f;
#pragma unroll
        for (int o = 16; o; o >>= 1) t = fmaxf(t, __shfl_xor_sync(~0u, t, o));
        if (tid == 0) sred[0] = t;
    }
    __syncthreads();
    float M = sred[0];
    __syncthreads();

    float s = 0.f;
    for (int i = tid; i < Vz / 4; i += 256) {
        float4 v = r4[i];
        s += __expf(v.x - M) + __expf(v.y - M) + __expf(v.z - M) + __expf(v.w - M);
    }
#pragma unroll
    for (int o = 16; o; o >>= 1) s += __shfl_xor_sync(~0u, s, o);
    if ((tid & 31) == 0) sred[tid >> 5] = s;
    __syncthreads();
    {
        float t = (tid < 8) ? sred[tid] : 0.f;
#pragma unroll
        for (int o = 16; o; o >>= 1) t += __shfl_xor_sync(~0u, t, o);
        if (tid == 0) sred[0] = t;
    }
    __syncthreads();
    float lse = M + logf(sred[0]);

    for (int i = tid; i < Vz / 4; i += 256) {
        float4 v = r4[i];
        v.x -= lse; v.y -= lse; v.z -= lse; v.w -= lse;
        r4[i] = v;
    }
}

// ---------------- driver ------------------------------------------------------
extern "C" void kernel_launch(void* const* d_in, const int* in_sizes, int n_in,
                              void* d_out, int out_size) {
    const int*   x     = (const int*)d_in[0];
    const int*   tgt   = (const int*)d_in[1];
    const float* emb   = (const float*)d_in[2];
    const float* eWih0 = (const float*)d_in[3];
    const float* eWhh0 = (const float*)d_in[4];
    const float* eb0   = (const float*)d_in[5];
    const float* eWih1 = (const float*)d_in[6];
    const float* eWhh1 = (const float*)d_in[7];
    const float* eb1   = (const float*)d_in[8];
    const float* dWih0 = (const float*)d_in[9];
    const float* dWhh0 = (const float*)d_in[10];
    const float* db0   = (const float*)d_in[11];
    const float* dWih1 = (const float*)d_in[12];
    const float* dWhh1 = (const float*)d_in[13];
    const float* db1   = (const float*)d_in[14];
    const float* fcW   = (const float*)d_in[15];
    const float* fcb   = (const float*)d_in[16];
    float* out = (float*)d_out;

    float *xg, *bufA, *bufB, *WT, *c, *hf0, *cf0, *hf1, *cf1, *zr;
    __nv_bfloat16 *Abf, *Wbf;
    cudaGetSymbolAddress((void**)&xg,   g_xg);
    cudaGetSymbolAddress((void**)&bufA, g_bufA);
    cudaGetSymbolAddress((void**)&bufB, g_bufB);
    cudaGetSymbolAddress((void**)&WT,   g_WT);
    cudaGetSymbolAddress((void**)&Abf,  g_Abf);
    cudaGetSymbolAddress((void**)&Wbf,  g_Wbf);
    cudaGetSymbolAddress((void**)&c,    g_c);
    cudaGetSymbolAddress((void**)&hf0,  g_hf0);
    cudaGetSymbolAddress((void**)&cf0,  g_cf0);
    cudaGetSymbolAddress((void**)&hf1,  g_hf1);
    cudaGetSymbolAddress((void**)&cf1,  g_cf1);
    cudaGetSymbolAddress((void**)&zr,   g_zero);

    const int BH = Bz * Hz;
    dim3 gGate(Gz / 128, TB / 128);       // (32, 32)
    dim3 gFC(Vz / 128, TB / 128);         // (250, 32)
    dim3 gT(128, 32), bT(32, 8);
    auto cgrid = [](int n) { return (n / 4 + 255) / 256; };

    // ---------- encoder layer 0 ----------
    embed_enc<<<TB, 128>>>(x, emb, bufA);
    f2bf<<<cgrid(TB * Ez), 256>>>(Abf, bufA, TB * Ez);
    f2bf<<<cgrid(Gz * Ez), 256>>>(Wbf, eWih0, Gz * Ez);
    bgemm<0><<<gGate, 256>>>(Abf, Wbf, eb0, xg, TB, Gz, Ez);
    transpose_wh<<<gT, bT>>>(eWhh0, WT);
    zero_k<<<BH / 256, 256>>>(zr, BH);
    zero_k<<<BH / 256, 256>>>(c, BH);
    for (int t = 0; t < Tz; t++) lstm_step<<<128, 128>>>(t, xg, WT, zr, bufB, c);
    copy_k<<<BH / 256, 256>>>(hf0, bufB + (size_t)(Tz - 1) * BH, BH);
    copy_k<<<BH / 256, 256>>>(cf0, c, BH);

    // ---------- encoder layer 1 ----------
    f2bf<<<cgrid(TB * Hz), 256>>>(Abf, bufB, TB * Hz);
    f2bf<<<cgrid(Gz * Hz), 256>>>(Wbf, eWih1, Gz * Hz);
    bgemm<0><<<gGate, 256>>>(Abf, Wbf, eb1, xg, TB, Gz, Hz);
    transpose_wh<<<gT, bT>>>(eWhh1, WT);
    zero_k<<<BH / 256, 256>>>(c, BH);
    for (int t = 0; t < Tz; t++) lstm_step<<<128, 128>>>(t, xg, WT, zr, bufA, c);
    copy_k<<<BH / 256, 256>>>(hf1, bufA + (size_t)(Tz - 1) * BH, BH);
    copy_k<<<BH / 256, 256>>>(cf1, c, BH);

    // ---------- decoder layer 0 (init = enc layer0 finals) ----------
    embed_dec<<<TB, 128>>>(tgt, emb, bufB);
    f2bf<<<cgrid(TB * Ez), 256>>>(Abf, bufB, TB * Ez);
    f2bf<<<cgrid(Gz * Ez), 256>>>(Wbf, dWih0, Gz * Ez);
    bgemm<0><<<gGate, 256>>>(Abf, Wbf, db0, xg, TB, Gz, Ez);
    transpose_wh<<<gT, bT>>>(dWhh0, WT);
    for (int t = 0; t < Tz; t++) lstm_step<<<128, 128>>>(t, xg, WT, hf0, bufA, cf0);

    // ---------- decoder layer 1 (init = enc layer1 finals) ----------
    f2bf<<<cgrid(TB * Hz), 256>>>(Abf, bufA, TB * Hz);
    f2bf<<<cgrid(Gz * Hz), 256>>>(Wbf, dWih1, Gz * Hz);
    bgemm<0><<<gGate, 256>>>(Abf, Wbf, db1, xg, TB, Gz, Hz);
    transpose_wh<<<gT, bT>>>(dWhh1, WT);
    for (int t = 0; t < Tz; t++) lstm_step<<<128, 128>>>(t, xg, WT, hf1, bufB, cf1);

    // ---------- FC projection (bf16 mma, fused b,t remap) + log_softmax -------
    f2bf<<<cgrid(TB * Hz), 256>>>(Abf, bufB, TB * Hz);
    f2bf<<<cgrid(Vz * Hz), 256>>>(Wbf, fcW, Vz * Hz);
    bgemm<1><<<gFC, 256>>>(Abf, Wbf, fcb, out, TB, Vz, Hz);
    logsoftmax_k<<<TB, 256>>>(out);
}

// round 11
// speedup vs baseline: 4.3531x; 3.3028x over previous
#include <cuda_runtime.h>
#include <cuda_bf16.h>
#include <math.h>
#include <stdint.h>

#define Bz 32
#define Tz 128
#define Ez 512
#define Hz 1024
#define Gz 4096   // 4*H
#define Vz 32000
#define TB 4096   // T*B
#define BH (Bz * Hz)
#define PITCH 40  // bgemm smem pitch
#define WP 1032   // lstm smem pitch (bf16 elems)

// ---------------- scratch (static device globals; no allocs allowed) ----------
__device__ float g_xg[(size_t)TB * Gz];               // 64 MB fp32 input gates
__device__ __nv_bfloat16 g_Wbf[(size_t)Vz * Hz];      // 64 MB bf16 GEMM weights
__device__ __nv_bfloat16 g_Whhbf[(size_t)Gz * Hz];    // 8 MB bf16 recurrent W
__device__ __nv_bfloat16 g_Hbf0[(size_t)TB * Hz];     // 8 MB h sequence (hi)
__device__ __nv_bfloat16 g_Hbf1[(size_t)TB * Hz];     // 8 MB h sequence (hi)
__device__ __nv_bfloat16 g_Abf[(size_t)TB * Ez];      // 4 MB embed bf16
__device__ __nv_bfloat16 g_hlo[2 * BH];               // h lo double buffer
__device__ __nv_bfloat16 g_zbf[BH];                   // zero bf16 h0
__device__ float g_zc[BH];                            // zero fp32 c0
__device__ __nv_bfloat16 g_hf0hi[BH], g_hf0lo[BH];
__device__ __nv_bfloat16 g_hf1hi[BH], g_hf1lo[BH];
__device__ float g_cf0[BH], g_cf1[BH];
__device__ __nv_bfloat16 g_dhfhi[BH], g_dhflo[BH];
__device__ float g_dc[BH];
__device__ unsigned g_barcnt;
__device__ unsigned g_barphase;

// ---------------- small helpers ----------------------------------------------
__global__ void zero_k(float* p, int n) {
    int i = blockIdx.x * blockDim.x + threadIdx.x;
    if (i < n) p[i] = 0.f;
}
__global__ void f2bf(__nv_bfloat16* __restrict__ d, const float* __restrict__ s, int n) {
    int i = (blockIdx.x * blockDim.x + threadIdx.x) * 4;
    if (i < n) {
        float4 v = *(const float4*)(s + i);
        __nv_bfloat162 lo = __floats2bfloat162_rn(v.x, v.y);
        __nv_bfloat162 hi = __floats2bfloat162_rn(v.z, v.w);
        uint2 pk;
        pk.x = *(uint32_t*)&lo;
        pk.y = *(uint32_t*)&hi;
        *(uint2*)(d + i) = pk;
    }
}
__device__ __forceinline__ uint32_t s2u(const void* p) {
    return (uint32_t)__cvta_generic_to_shared(p);
}
__device__ __forceinline__ float sigm(float x) { return 1.f / (1.f + expf(-x)); }

// ---------------- embedding gathers -> bf16 [T,B,E] ---------------------------
__global__ void embed_enc(const int* __restrict__ x, const float* __restrict__ emb,
                          __nv_bfloat16* __restrict__ out) {
    int tb = blockIdx.x;
    int t = tb >> 5, b = tb & 31;
    int tok = x[b * Tz + t];
    float4 v = ((const float4*)(emb + (size_t)tok * Ez))[threadIdx.x];
    __nv_bfloat162 lo = __floats2bfloat162_rn(v.x, v.y);
    __nv_bfloat162 hi = __floats2bfloat162_rn(v.z, v.w);
    uint2 pk; pk.x = *(uint32_t*)&lo; pk.y = *(uint32_t*)&hi;
    *(uint2*)(out + (size_t)tb * Ez + threadIdx.x * 4) = pk;
}
__global__ void embed_dec(const int* __restrict__ tgt, const float* __restrict__ emb,
                          __nv_bfloat16* __restrict__ out) {
    int tb = blockIdx.x;
    int t = tb >> 5, b = tb & 31;
    int tok = (t == 0) ? 0 : tgt[b * Tz + t - 1];
    float4 v = ((const float4*)(emb + (size_t)tok * Ez))[threadIdx.x];
    __nv_bfloat162 lo = __floats2bfloat162_rn(v.x, v.y);
    __nv_bfloat162 hi = __floats2bfloat162_rn(v.z, v.w);
    uint2 pk; pk.x = *(uint32_t*)&lo; pk.y = *(uint32_t*)&hi;
    *(uint2*)(out + (size_t)tb * Ez + threadIdx.x * 4) = pk;
}

// ---------------- bf16 tensor-core GEMM ---------------------------------------
template <int REMAP>
__global__ __launch_bounds__(256)
void bgemm(const __nv_bfloat16* __restrict__ A, const __nv_bfloat16* __restrict__ W,
           const float* __restrict__ bias, float* __restrict__ C,
           int M, int N, int K) {
    __shared__ __nv_bfloat16 As[128 * PITCH];
    __shared__ __nv_bfloat16 Ws[128 * PITCH];

    int tid = threadIdx.x;
    int wid = tid >> 5, lane = tid & 31;
    int wm = wid >> 2;
    int wn = wid & 3;
    int m0 = blockIdx.y * 128;
    int n0 = blockIdx.x * 128;

    float acc[4][4][4];
#pragma unroll
    for (int a = 0; a < 4; a++)
#pragma unroll
        for (int b = 0; b < 4; b++)
#pragma unroll
            for (int cidx = 0; cidx < 4; cidx++) acc[a][b][cidx] = 0.f;

    for (int k0 = 0; k0 < K; k0 += 32) {
#pragma unroll
        for (int s = 0; s < 2; s++) {
            int c = tid + s * 256;
            int row = c >> 2, seg = c & 3;
            uint4 va = *(const uint4*)(A + (size_t)(m0 + row) * K + k0 + seg * 8);
            *(uint4*)(As + row * PITCH + seg * 8) = va;
            uint4 vw = *(const uint4*)(W + (size_t)(n0 + row) * K + k0 + seg * 8);
            *(uint4*)(Ws + row * PITCH + seg * 8) = vw;
        }
        __syncthreads();

#pragma unroll
        for (int ks = 0; ks < 32; ks += 16) {
            uint32_t afr[4][4];
            uint32_t bfr[4][2];
#pragma unroll
            for (int mt = 0; mt < 4; mt++) {
                int row = wm * 64 + mt * 16 + (lane & 15);
                int col = ks + ((lane >> 4) << 3);
                uint32_t addr = s2u(As + row * PITCH + col);
                asm volatile(
                    "ldmatrix.sync.aligned.m8n8.x4.shared.b16 {%0,%1,%2,%3},[%4];"
                    : "=r"(afr[mt][0]), "=r"(afr[mt][1]), "=r"(afr[mt][2]), "=r"(afr[mt][3])
                    : "r"(addr));
            }
#pragma unroll
            for (int nt = 0; nt < 4; nt++) {
                int row = wn * 32 + nt * 8 + (lane & 7);
                int col = ks + (((lane >> 3) & 1) << 3);
                uint32_t addr = s2u(Ws + row * PITCH + col);
                asm volatile(
                    "ldmatrix.sync.aligned.m8n8.x2.shared.b16 {%0,%1},[%2];"
                    : "=r"(bfr[nt][0]), "=r"(bfr[nt][1])
                    : "r"(addr));
            }
#pragma unroll
            for (int mt = 0; mt < 4; mt++)
#pragma unroll
                for (int nt = 0; nt < 4; nt++) {
                    asm volatile(
                        "mma.sync.aligned.m16n8k16.row.col.f32.bf16.bf16.f32 "
                        "{%0,%1,%2,%3},{%4,%5,%6,%7},{%8,%9},{%0,%1,%2,%3};"
                        : "+f"(acc[mt][nt][0]), "+f"(acc[mt][nt][1]),
                          "+f"(acc[mt][nt][2]), "+f"(acc[mt][nt][3])
                        : "r"(afr[mt][0]), "r"(afr[mt][1]), "r"(afr[mt][2]), "r"(afr[mt][3]),
                          "r"(bfr[nt][0]), "r"(bfr[nt][1]));
                }
        }
        __syncthreads();
    }

#pragma unroll
    for (int mt = 0; mt < 4; mt++) {
#pragma unroll
        for (int nt = 0; nt < 4; nt++) {
            int col = n0 + wn * 32 + nt * 8 + (lane & 3) * 2;
            float b0 = bias[col], b1 = bias[col + 1];
#pragma unroll
            for (int half = 0; half < 2; half++) {
                int m = m0 + wm * 64 + mt * 16 + (lane >> 2) + half * 8;
                float2 v;
                v.x = acc[mt][nt][half * 2 + 0] + b0;
                v.y = acc[mt][nt][half * 2 + 1] + b1;
                if (REMAP) {
                    int b = m & 31, t = m >> 5;
                    *(float2*)(C + ((size_t)b * Tz + t) * Vz + col) = v;
                } else {
                    *(float2*)(C + (size_t)m * N + col) = v;
                }
            }
        }
    }
}

// ---------------- persistent LSTM layer ---------------------------------------
#define OFF_W 0
#define OFF_H (OFF_W + 32 * WP * 2)
#define OFF_P (OFF_H + 64 * WP * 2)
#define OFF_G (OFF_P + 2 * 32 * 33 * 4)
#define OFF_C (OFF_G + 32 * 33 * 4)
#define LSTM_SMEM (OFF_C + 256 * 4)

__device__ __forceinline__ void gridbar(unsigned& phase) {
    __threadfence();
    __syncthreads();
    if (threadIdx.x == 0) {
        unsigned tgt = phase + 1;
        unsigned old = atomicAdd(&g_barcnt, 1);
        if (old == gridDim.x - 1) {
            atomicExch(&g_barcnt, 0);
            __threadfence();
            atomicExch(&g_barphase, tgt);
        } else {
            while (*(volatile unsigned*)&g_barphase != tgt) __nanosleep(32);
        }
        phase = tgt;
    }
    __syncthreads();
}

__global__ __launch_bounds__(256, 1)
void lstm_layer(const float* __restrict__ xg,
                const __nv_bfloat16* __restrict__ Wbf,
                const __nv_bfloat16* __restrict__ h0hi,
                const __nv_bfloat16* __restrict__ h0lo,
                const float* __restrict__ c_init,
                __nv_bfloat16* __restrict__ Hhi,
                __nv_bfloat16* __restrict__ hlo,
                __nv_bfloat16* __restrict__ hf_hi,
                __nv_bfloat16* __restrict__ hf_lo,
                float* __restrict__ c_final) {
    extern __shared__ char smem[];
    __nv_bfloat16* Wsm = (__nv_bfloat16*)(smem + OFF_W);   // [32][WP]
    __nv_bfloat16* Hsm = (__nv_bfloat16*)(smem + OFF_H);   // [64][WP]
    float* part = (float*)(smem + OFF_P);                  // [2][32][33]
    float* gsm  = (float*)(smem + OFF_G);                  // [32][33]
    float* csm  = (float*)(smem + OFF_C);                  // [256]

    const int tid = threadIdx.x;
    const int wid = tid >> 5, lane = tid & 31;
    const int kw = wid >> 2;
    const int nw = wid & 3;
    const int j0 = blockIdx.x * 8;

#pragma unroll
    for (int u = 0; u < 16; u++) {
        int c = tid + 256 * u;
        int r = c >> 7, seg = c & 127;
        int grow = (r >> 3) * Hz + j0 + (r & 7);
        uint4 v = *(const uint4*)(Wbf + (size_t)grow * Hz + seg * 8);
        *(uint4*)(Wsm + r * WP + seg * 8) = v;
    }
    {
        int b = tid >> 3, j = tid & 7;
        csm[tid] = c_init[b * Hz + j0 + j];
    }
    unsigned phase = 0;
    if (tid == 0) phase = *(volatile unsigned*)&g_barphase;

    for (int t = 0; t < Tz; t++) {
        const __nv_bfloat16* shi = (t == 0) ? h0hi : (Hhi + (size_t)(t - 1) * BH);
        const __nv_bfloat16* slo = (t == 0) ? h0lo : (hlo + (size_t)((t - 1) & 1) * BH);
#pragma unroll
        for (int u = 0; u < 16; u++) {
            int c = tid + 256 * u;
            int r = c >> 7, seg = c & 127;
            uint4 vh = __ldcv((const uint4*)(shi + (size_t)r * Hz) + seg);
            *(uint4*)(Hsm + r * WP + seg * 8) = vh;
            uint4 vl = __ldcv((const uint4*)(slo + (size_t)r * Hz) + seg);
            *(uint4*)(Hsm + (size_t)(32 + r) * WP + seg * 8) = vl;
        }
        __syncthreads();

        float acc[2][4];
#pragma unroll
        for (int a = 0; a < 2; a++)
#pragma unroll
            for (int b = 0; b < 4; b++) acc[a][b] = 0.f;

        for (int ks = 0; ks < 512; ks += 16) {
            int k = kw * 512 + ks;
            uint32_t bfr[2];
            {
                uint32_t addr = s2u(Wsm + (nw * 8 + (lane & 7)) * WP + k + (((lane >> 3) & 1) << 3));
                asm volatile(
                    "ldmatrix.sync.aligned.m8n8.x2.shared.b16 {%0,%1},[%2];"
                    : "=r"(bfr[0]), "=r"(bfr[1]) : "r"(addr));
            }
#pragma unroll
            for (int half = 0; half < 2; half++) {
#pragma unroll
                for (int mt = 0; mt < 2; mt++) {
                    uint32_t afr[4];
                    int row = half * 32 + mt * 16 + (lane & 15);
                    uint32_t addr = s2u(Hsm + row * WP + k + ((lane >> 4) << 3));
                    asm volatile(
                        "ldmatrix.sync.aligned.m8n8.x4.shared.b16 {%0,%1,%2,%3},[%4];"
                        : "=r"(afr[0]), "=r"(afr[1]), "=r"(afr[2]), "=r"(afr[3])
                        : "r"(addr));
                    asm volatile(
                        "mma.sync.aligned.m16n8k16.row.col.f32.bf16.bf16.f32 "
                        "{%0,%1,%2,%3},{%4,%5,%6,%7},{%8,%9},{%0,%1,%2,%3};"
                        : "+f"(acc[mt][0]), "+f"(acc[mt][1]),
                          "+f"(acc[mt][2]), "+f"(acc[mt][3])
                        : "r"(afr[0]), "r"(afr[1]), "r"(afr[2]), "r"(afr[3]),
                          "r"(bfr[0]), "r"(bfr[1]));
                }
            }
        }
        {
            int r0 = lane >> 2, c0 = (lane & 3) * 2;
#pragma unroll
            for (int mt = 0; mt < 2; mt++) {
                float* p = part + (kw * 32 + mt * 16 + r0) * 33 + nw * 8 + c0;
                p[0] = acc[mt][0]; p[1] = acc[mt][1];
                p[8 * 33] = acc[mt][2]; p[8 * 33 + 1] = acc[mt][3];
            }
        }
        __syncthreads();

#pragma unroll
        for (int u = 0; u < 4; u++) {
            int id = tid + 256 * u;
            int m = id >> 5, n = id & 31;
            int gcol = (n >> 3) * Hz + j0 + (n & 7);
            float v = part[m * 33 + n] + part[(32 + m) * 33 + n]
                    + xg[((size_t)t * Bz + m) * Gz + gcol];
            gsm[m * 33 + n] = v;
        }
        __syncthreads();

        {
            int b = tid >> 3, j = tid & 7;
            float iv = gsm[b * 33 + j];
            float fv = gsm[b * 33 + 8 + j];
            float gv = gsm[b * 33 + 16 + j];
            float ov = gsm[b * 33 + 24 + j];
            float cn = sigm(fv) * csm[tid] + sigm(iv) * tanhf(gv);
            csm[tid] = cn;
            float hv = sigm(ov) * tanhf(cn);
            __nv_bfloat16 hb = __float2bfloat16(hv);
            __nv_bfloat16 lb = __float2bfloat16(hv - __bfloat162float(hb));
            int idx = b * Hz + j0 + j;
            Hhi[(size_t)t * BH + idx] = hb;
            hlo[(size_t)(t & 1) * BH + idx] = lb;
            if (t == Tz - 1) {
                hf_hi[idx] = hb;
                hf_lo[idx] = lb;
                c_final[idx] = cn;
            }
        }
        if (t < Tz - 1) gridbar(phase);   // last step ordered by kernel boundary
    }
}

// ---------------- in-place log_softmax ----------------------------------------
__global__ __launch_bounds__(256)
void logsoftmax_k(float* __restrict__ out) {
    float* row = out + (size_t)blockIdx.x * Vz;
    float4* r4 = (float4*)row;
    const int tid = threadIdx.x;
    __shared__ float sred[32];

    float m = -1e30f;
    for (int i = tid; i < Vz / 4; i += 256) {
        float4 v = r4[i];
        m = fmaxf(m, fmaxf(fmaxf(v.x, v.y), fmaxf(v.z, v.w)));
    }
#pragma unroll
    for (int o = 16; o; o >>= 1) m = fmaxf(m, __shfl_xor_sync(~0u, m, o));
    if ((tid & 31) == 0) sred[tid >> 5] = m;
    __syncthreads();
    {
        float t = (tid < 8) ? sred[tid] : -1e30f;
#pragma unroll
        for (int o = 16; o; o >>= 1) t = fmaxf(t, __shfl_xor_sync(~0u, t, o));
        if (tid == 0) sred[0] = t;
    }
    __syncthreads();
    float M = sred[0];
    __syncthreads();

    float s = 0.f;
    for (int i = tid; i < Vz / 4; i += 256) {
        float4 v = r4[i];
        s += __expf(v.x - M) + __expf(v.y - M) + __expf(v.z - M) + __expf(v.w - M);
    }
#pragma unroll
    for (int o = 16; o; o >>= 1) s += __shfl_xor_sync(~0u, s, o);
    if ((tid & 31) == 0) sred[tid >> 5] = s;
    __syncthreads();
    {
        float t = (tid < 8) ? sred[tid] : 0.f;
#pragma unroll
        for (int o = 16; o; o >>= 1) t += __shfl_xor_sync(~0u, t, o);
        if (tid == 0) sred[0] = t;
    }
    __syncthreads();
    float lse = M + logf(sred[0]);

    for (int i = tid; i < Vz / 4; i += 256) {
        float4 v = r4[i];
        v.x -= lse; v.y -= lse; v.z -= lse; v.w -= lse;
        r4[i] = v;
    }
}

// ---------------- driver ------------------------------------------------------
extern "C" void kernel_launch(void* const* d_in, const int* in_sizes, int n_in,
                              void* d_out, int out_size) {
    const int*   x     = (const int*)d_in[0];
    const int*   tgt   = (const int*)d_in[1];
    const float* emb   = (const float*)d_in[2];
    const float* eWih0 = (const float*)d_in[3];
    const float* eWhh0 = (const float*)d_in[4];
    const float* eb0   = (const float*)d_in[5];
    const float* eWih1 = (const float*)d_in[6];
    const float* eWhh1 = (const float*)d_in[7];
    const float* eb1   = (const float*)d_in[8];
    const float* dWih0 = (const float*)d_in[9];
    const float* dWhh0 = (const float*)d_in[10];
    const float* db0   = (const float*)d_in[11];
    const float* dWih1 = (const float*)d_in[12];
    const float* dWhh1 = (const float*)d_in[13];
    const float* db1   = (const float*)d_in[14];
    const float* fcW   = (const float*)d_in[15];
    const float* fcb   = (const float*)d_in[16];
    float* out = (float*)d_out;

    float *xg, *zc, *cf0, *cf1, *dc;
    __nv_bfloat16 *Wbf, *Whhbf, *Hbf0, *Hbf1, *Abf, *hlo, *zbf;
    __nv_bfloat16 *hf0hi, *hf0lo, *hf1hi, *hf1lo, *dhfhi, *dhflo;
    cudaGetSymbolAddress((void**)&xg,    g_xg);
    cudaGetSymbolAddress((void**)&Wbf,   g_Wbf);
    cudaGetSymbolAddress((void**)&Whhbf, g_Whhbf);
    cudaGetSymbolAddress((void**)&Hbf0,  g_Hbf0);
    cudaGetSymbolAddress((void**)&Hbf1,  g_Hbf1);
    cudaGetSymbolAddress((void**)&Abf,   g_Abf);
    cudaGetSymbolAddress((void**)&hlo,   g_hlo);
    cudaGetSymbolAddress((void**)&zbf,   g_zbf);
    cudaGetSymbolAddress((void**)&zc,    g_zc);
    cudaGetSymbolAddress((void**)&hf0hi, g_hf0hi);
    cudaGetSymbolAddress((void**)&hf0lo, g_hf0lo);
    cudaGetSymbolAddress((void**)&hf1hi, g_hf1hi);
    cudaGetSymbolAddress((void**)&hf1lo, g_hf1lo);
    cudaGetSymbolAddress((void**)&cf0,   g_cf0);
    cudaGetSymbolAddress((void**)&cf1,   g_cf1);
    cudaGetSymbolAddress((void**)&dhfhi, g_dhfhi);
    cudaGetSymbolAddress((void**)&dhflo, g_dhflo);
    cudaGetSymbolAddress((void**)&dc,    g_dc);

    cudaFuncSetAttribute(lstm_layer, cudaFuncAttributeMaxDynamicSharedMemorySize, LSTM_SMEM);

    dim3 gGate(Gz / 128, TB / 128);
    dim3 gFC(Vz / 128, TB / 128);
    auto cgrid = [](int n) { return (n / 4 + 255) / 256; };

    zero_k<<<BH / 256, 256>>>(zc, BH);
    zero_k<<<(BH / 2) / 256, 256>>>((float*)zbf, BH / 2);

    // ---------- encoder layer 0 ----------
    embed_enc<<<TB, 128>>>(x, emb, Abf);
    f2bf<<<cgrid(Gz * Ez), 256>>>(Wbf, eWih0, Gz * Ez);
    bgemm<0><<<gGate, 256>>>(Abf, Wbf, eb0, xg, TB, Gz, Ez);
    f2bf<<<cgrid(Gz * Hz), 256>>>(Whhbf, eWhh0, Gz * Hz);
    lstm_layer<<<128, 256, LSTM_SMEM>>>(xg, Whhbf, zbf, zbf, zc, Hbf0, hlo,
                                        hf0hi, hf0lo, cf0);

    // ---------- encoder layer 1 ----------
    f2bf<<<cgrid(Gz * Hz), 256>>>(Wbf, eWih1, Gz * Hz);
    bgemm<0><<<gGate, 256>>>(Hbf0, Wbf, eb1, xg, TB, Gz, Hz);
    f2bf<<<cgrid(Gz * Hz), 256>>>(Whhbf, eWhh1, Gz * Hz);
    lstm_layer<<<128, 256, LSTM_SMEM>>>(xg, Whhbf, zbf, zbf, zc, Hbf1, hlo,
                                        hf1hi, hf1lo, cf1);

    // ---------- decoder layer 0 (init = enc layer0 finals) ----------
    embed_dec<<<TB, 128>>>(tgt, emb, Abf);
    f2bf<<<cgrid(Gz * Ez), 256>>>(Wbf, dWih0, Gz * Ez);
    bgemm<0><<<gGate, 256>>>(Abf, Wbf, db0, xg, TB, Gz, Ez);
    f2bf<<<cgrid(Gz * Hz), 256>>>(Whhbf, dWhh0, Gz * Hz);
    lstm_layer<<<128, 256, LSTM_SMEM>>>(xg, Whhbf, hf0hi, hf0lo, cf0, Hbf0, hlo,
                                        dhfhi, dhflo, dc);

    // ---------- decoder layer 1 (init = enc layer1 finals) ----------
    f2bf<<<cgrid(Gz * Hz), 256>>>(Wbf, dWih1, Gz * Hz);
    bgemm<0><<<gGate, 256>>>(Hbf0, Wbf, db1, xg, TB, Gz, Hz);
    f2bf<<<cgrid(Gz * Hz), 256>>>(Whhbf, dWhh1, Gz * Hz);
    lstm_layer<<<128, 256, LSTM_SMEM>>>(xg, Whhbf, hf1hi, hf1lo, cf1, Hbf1, hlo,
                                        dhfhi, dhflo, dc);

    // ---------- FC projection (fused b,t remap) + log_softmax ----------
    f2bf<<<cgrid(Vz * Hz), 256>>>(Wbf, fcW, Vz * Hz);
    bgemm<1><<<gFC, 256>>>(Hbf1, Wbf, fcb, out, TB, Vz, Hz);
    logsoftmax_k<<<TB, 256>>>(out);
}

// round 12
// speedup vs baseline: 4.6488x; 1.0679x over previous
#include <cuda_runtime.h>
#include <cuda_bf16.h>
#include <math.h>
#include <stdint.h>

#define Bz 32
#define Tz 128
#define Ez 512
#define Hz 1024
#define Gz 4096   // 4*H
#define Vz 32000
#define TB 4096   // T*B
#define BH (Bz * Hz)
#define PITCH 40  // bgemm smem pitch
#define WP 1032   // lstm smem pitch (bf16 elems)

// ---------------- scratch (static device globals; no allocs allowed) ----------
__device__ float g_xg[(size_t)TB * Gz];               // 64 MB fp32 input gates
__device__ __nv_bfloat16 g_Wbf[(size_t)Vz * Hz];      // 64 MB bf16 GEMM weights
__device__ __nv_bfloat16 g_Whhbf[(size_t)Gz * Hz];    // 8 MB bf16 recurrent W
__device__ __nv_bfloat16 g_Hbf0[(size_t)TB * Hz];     // 8 MB h sequence (hi)
__device__ __nv_bfloat16 g_Hbf1[(size_t)TB * Hz];     // 8 MB h sequence (hi)
__device__ __nv_bfloat16 g_Abf[(size_t)TB * Ez];      // 4 MB embed bf16
__device__ __nv_bfloat16 g_hlo[2 * BH];               // h lo double buffer
__device__ __nv_bfloat16 g_zbf[BH];                   // zero bf16 h0
__device__ float g_zc[BH];                            // zero fp32 c0
__device__ __nv_bfloat16 g_hf0hi[BH], g_hf0lo[BH];
__device__ __nv_bfloat16 g_hf1hi[BH], g_hf1lo[BH];
__device__ float g_cf0[BH], g_cf1[BH];
__device__ __nv_bfloat16 g_dhfhi[BH], g_dhflo[BH];
__device__ float g_dc[BH];
__device__ unsigned g_cnt[8 * 32];   // bucket counters, 128B apart
__device__ unsigned g_root;
__device__ unsigned g_barphase;

// ---------------- small helpers ----------------------------------------------
__global__ void zero_k(float* p, int n) {
    int i = blockIdx.x * blockDim.x + threadIdx.x;
    if (i < n) p[i] = 0.f;
}
__global__ void f2bf(__nv_bfloat16* __restrict__ d, const float* __restrict__ s, int n) {
    int i = (blockIdx.x * blockDim.x + threadIdx.x) * 4;
    if (i < n) {
        float4 v = *(const float4*)(s + i);
        __nv_bfloat162 lo = __floats2bfloat162_rn(v.x, v.y);
        __nv_bfloat162 hi = __floats2bfloat162_rn(v.z, v.w);
        uint2 pk;
        pk.x = *(uint32_t*)&lo;
        pk.y = *(uint32_t*)&hi;
        *(uint2*)(d + i) = pk;
    }
}
__device__ __forceinline__ uint32_t s2u(const void* p) {
    return (uint32_t)__cvta_generic_to_shared(p);
}
__device__ __forceinline__ void cp16(void* dst, const void* src) {
    uint32_t d = s2u(dst);
    asm volatile("cp.async.cg.shared.global [%0], [%1], 16;" :: "r"(d), "l"(src));
}
#define CP_COMMIT asm volatile("cp.async.commit_group;" ::: "memory")
#define CP_WAIT0  asm volatile("cp.async.wait_group 0;" ::: "memory")
#define CP_WAIT1  asm volatile("cp.async.wait_group 1;" ::: "memory")
__device__ __forceinline__ float sigm(float x) { return 1.f / (1.f + expf(-x)); }

// ---------------- embedding gathers -> bf16 [T,B,E] ---------------------------
__global__ void embed_enc(const int* __restrict__ x, const float* __restrict__ emb,
                          __nv_bfloat16* __restrict__ out) {
    int tb = blockIdx.x;
    int t = tb >> 5, b = tb & 31;
    int tok = x[b * Tz + t];
    float4 v = ((const float4*)(emb + (size_t)tok * Ez))[threadIdx.x];
    __nv_bfloat162 lo = __floats2bfloat162_rn(v.x, v.y);
    __nv_bfloat162 hi = __floats2bfloat162_rn(v.z, v.w);
    uint2 pk; pk.x = *(uint32_t*)&lo; pk.y = *(uint32_t*)&hi;
    *(uint2*)(out + (size_t)tb * Ez + threadIdx.x * 4) = pk;
}
__global__ void embed_dec(const int* __restrict__ tgt, const float* __restrict__ emb,
                          __nv_bfloat16* __restrict__ out) {
    int tb = blockIdx.x;
    int t = tb >> 5, b = tb & 31;
    int tok = (t == 0) ? 0 : tgt[b * Tz + t - 1];
    float4 v = ((const float4*)(emb + (size_t)tok * Ez))[threadIdx.x];
    __nv_bfloat162 lo = __floats2bfloat162_rn(v.x, v.y);
    __nv_bfloat162 hi = __floats2bfloat162_rn(v.z, v.w);
    uint2 pk; pk.x = *(uint32_t*)&lo; pk.y = *(uint32_t*)&hi;
    *(uint2*)(out + (size_t)tb * Ez + threadIdx.x * 4) = pk;
}

// ---------------- bf16 tensor-core GEMM, cp.async double-buffered -------------
__device__ __forceinline__ void bg_load(int tid, __nv_bfloat16* As, __nv_bfloat16* Ws,
                                        const __nv_bfloat16* A, const __nv_bfloat16* W,
                                        int m0, int n0, int K, int k0) {
#pragma unroll
    for (int s = 0; s < 2; s++) {
        int c = tid + s * 256;
        int row = c >> 2, seg = c & 3;
        cp16(As + row * PITCH + seg * 8, A + (size_t)(m0 + row) * K + k0 + seg * 8);
        cp16(Ws + row * PITCH + seg * 8, W + (size_t)(n0 + row) * K + k0 + seg * 8);
    }
    CP_COMMIT;
}

template <int REMAP>
__global__ __launch_bounds__(256)
void bgemm(const __nv_bfloat16* __restrict__ A, const __nv_bfloat16* __restrict__ W,
           const float* __restrict__ bias, float* __restrict__ C,
           int M, int N, int K) {
    __shared__ __nv_bfloat16 As[2][128 * PITCH];
    __shared__ __nv_bfloat16 Ws[2][128 * PITCH];

    int tid = threadIdx.x;
    int wid = tid >> 5, lane = tid & 31;
    int wm = wid >> 2;
    int wn = wid & 3;
    int m0 = blockIdx.y * 128;
    int n0 = blockIdx.x * 128;

    float acc[4][4][4];
#pragma unroll
    for (int a = 0; a < 4; a++)
#pragma unroll
        for (int b = 0; b < 4; b++)
#pragma unroll
            for (int cidx = 0; cidx < 4; cidx++) acc[a][b][cidx] = 0.f;

    bg_load(tid, As[0], Ws[0], A, W, m0, n0, K, 0);
    const int KT = K >> 5;

    for (int kt = 0; kt < KT; kt++) {
        CP_WAIT0;
        __syncthreads();
        if (kt + 1 < KT)
            bg_load(tid, As[(kt + 1) & 1], Ws[(kt + 1) & 1], A, W, m0, n0, K, (kt + 1) * 32);
        const __nv_bfloat16* Ab = As[kt & 1];
        const __nv_bfloat16* Wb = Ws[kt & 1];

#pragma unroll
        for (int ks = 0; ks < 32; ks += 16) {
            uint32_t afr[4][4];
            uint32_t bfr[4][2];
#pragma unroll
            for (int mt = 0; mt < 4; mt++) {
                int row = wm * 64 + mt * 16 + (lane & 15);
                int col = ks + ((lane >> 4) << 3);
                uint32_t addr = s2u(Ab + row * PITCH + col);
                asm volatile(
                    "ldmatrix.sync.aligned.m8n8.x4.shared.b16 {%0,%1,%2,%3},[%4];"
                    : "=r"(afr[mt][0]), "=r"(afr[mt][1]), "=r"(afr[mt][2]), "=r"(afr[mt][3])
                    : "r"(addr));
            }
#pragma unroll
            for (int nt = 0; nt < 4; nt++) {
                int row = wn * 32 + nt * 8 + (lane & 7);
                int col = ks + (((lane >> 3) & 1) << 3);
                uint32_t addr = s2u(Wb + row * PITCH + col);
                asm volatile(
                    "ldmatrix.sync.aligned.m8n8.x2.shared.b16 {%0,%1},[%2];"
                    : "=r"(bfr[nt][0]), "=r"(bfr[nt][1])
                    : "r"(addr));
            }
#pragma unroll
            for (int mt = 0; mt < 4; mt++)
#pragma unroll
                for (int nt = 0; nt < 4; nt++) {
                    asm volatile(
                        "mma.sync.aligned.m16n8k16.row.col.f32.bf16.bf16.f32 "
                        "{%0,%1,%2,%3},{%4,%5,%6,%7},{%8,%9},{%0,%1,%2,%3};"
                        : "+f"(acc[mt][nt][0]), "+f"(acc[mt][nt][1]),
                          "+f"(acc[mt][nt][2]), "+f"(acc[mt][nt][3])
                        : "r"(afr[mt][0]), "r"(afr[mt][1]), "r"(afr[mt][2]), "r"(afr[mt][3]),
                          "r"(bfr[nt][0]), "r"(bfr[nt][1]));
                }
        }
    }

#pragma unroll
    for (int mt = 0; mt < 4; mt++) {
#pragma unroll
        for (int nt = 0; nt < 4; nt++) {
            int col = n0 + wn * 32 + nt * 8 + (lane & 3) * 2;
            float b0 = bias[col], b1 = bias[col + 1];
#pragma unroll
            for (int half = 0; half < 2; half++) {
                int m = m0 + wm * 64 + mt * 16 + (lane >> 2) + half * 8;
                float2 v;
                v.x = acc[mt][nt][half * 2 + 0] + b0;
                v.y = acc[mt][nt][half * 2 + 1] + b1;
                if (REMAP) {
                    int b = m & 31, t = m >> 5;
                    *(float2*)(C + ((size_t)b * Tz + t) * Vz + col) = v;
                } else {
                    *(float2*)(C + (size_t)m * N + col) = v;
                }
            }
        }
    }
}

// ---------------- persistent LSTM layer ---------------------------------------
#define OFF_W 0
#define OFF_H (OFF_W + 32 * WP * 2)
#define OFF_G (OFF_H + 64 * WP * 2)
#define OFF_C (OFF_G + 32 * 33 * 4)
#define LSTM_SMEM (OFF_C + 256 * 4)

__device__ __forceinline__ void gridbar(unsigned& phase) {
    __threadfence();
    __syncthreads();
    if (threadIdx.x == 0) {
        unsigned tgt = phase + 1;
        int bkt = (blockIdx.x & 7) * 32;
        if (atomicAdd(&g_cnt[bkt], 1) == 15) {
            atomicExch(&g_cnt[bkt], 0);
            if (atomicAdd(&g_root, 1) == 7) {
                atomicExch(&g_root, 0);
                __threadfence();
                atomicExch(&g_barphase, tgt);
            }
        }
        while (*(volatile unsigned*)&g_barphase != tgt) { }
        phase = tgt;
    }
    __syncthreads();
}

__global__ __launch_bounds__(256, 1)
void lstm_layer(const float* __restrict__ xg,
                const __nv_bfloat16* __restrict__ Wbf,
                const __nv_bfloat16* __restrict__ h0hi,
                const __nv_bfloat16* __restrict__ h0lo,
                const float* __restrict__ c_init,
                __nv_bfloat16* __restrict__ Hhi,
                __nv_bfloat16* __restrict__ hlo,
                __nv_bfloat16* __restrict__ hf_hi,
                __nv_bfloat16* __restrict__ hf_lo,
                float* __restrict__ c_final) {
    extern __shared__ char smem[];
    __nv_bfloat16* Wsm = (__nv_bfloat16*)(smem + OFF_W);   // [32][WP]
    __nv_bfloat16* Hsm = (__nv_bfloat16*)(smem + OFF_H);   // [64][WP]: hi rows 0-31, lo 32-63
    float* gsm = (float*)(smem + OFF_G);                   // [32][33]
    float* csm = (float*)(smem + OFF_C);                   // [256]

    const int tid = threadIdx.x;
    const int wid = tid >> 5, lane = tid & 31;
    const int mt = wid >> 2;          // batch half (rows mt*16..+16)
    const int nw = wid & 3;           // gate index (8 cols each)
    const int j0 = blockIdx.x * 8;

    // one-time: W slice (32 gate cols x 1024 K) into smem
#pragma unroll
    for (int u = 0; u < 16; u++) {
        int c = tid + 256 * u;
        int r = c >> 7, seg = c & 127;
        int grow = (r >> 3) * Hz + j0 + (r & 7);
        uint4 v = *(const uint4*)(Wbf + (size_t)grow * Hz + seg * 8);
        *(uint4*)(Wsm + r * WP + seg * 8) = v;
    }
    {
        int b = tid >> 3, j = tid & 7;
        csm[tid] = c_init[b * Hz + j0 + j];
    }
    unsigned phase = 0;
    if (tid == 0) phase = *(volatile unsigned*)&g_barphase;
    __syncthreads();

    // per-thread output coordinates (warp computes one 16x8 gate tile)
    const int r0 = mt * 16 + (lane >> 2);        // batch row
    const int cc = (lane & 3) * 2;               // col pair within gate

    for (int t = 0; t < Tz; t++) {
        const __nv_bfloat16* shi = (t == 0) ? h0hi : (Hhi + (size_t)(t - 1) * BH);
        const __nv_bfloat16* slo = (t == 0) ? h0lo : (hlo + (size_t)((t - 1) & 1) * BH);

        // prefetch xg for this thread's 4 output gates
        const float* xp = xg + ((size_t)t * Bz + r0) * Gz + nw * Hz + j0 + cc;
        float2 xv01 = *(const float2*)xp;
        float2 xv23 = *(const float2*)(xp + 8 * Gz);

        // chunked cp.async staging of h hi+lo, overlapped with MMA
        // chunk = 256 K-cols; per chunk 8 cp16/thread
#define STAGE_CHUNK(CK) do {                                               \
        int kc_ = (CK) * 256;                                              \
        _Pragma("unroll")                                                  \
        for (int u = 0; u < 4; u++) {                                      \
            int c_ = tid + 256 * u;                                        \
            int r_ = c_ >> 5, sg_ = c_ & 31;                               \
            cp16(Hsm + r_ * WP + kc_ + sg_ * 8,                            \
                 shi + (size_t)r_ * Hz + kc_ + sg_ * 8);                   \
            cp16(Hsm + (32 + r_) * WP + kc_ + sg_ * 8,                     \
                 slo + (size_t)r_ * Hz + kc_ + sg_ * 8);                   \
        }                                                                  \
        CP_COMMIT; } while (0)

        STAGE_CHUNK(0);

        float acc[4] = {0.f, 0.f, 0.f, 0.f};

        for (int ck = 0; ck < 4; ck++) {
            if (ck + 1 < 4) STAGE_CHUNK(ck + 1);
            if (ck + 1 < 4) { CP_WAIT1; } else { CP_WAIT0; }
            __syncthreads();
            int kc = ck * 256;
#pragma unroll
            for (int ki = 0; ki < 16; ki++) {
                int k = kc + (ki << 4);
                uint32_t b0, b1;
                {
                    uint32_t addr = s2u(Wsm + (nw * 8 + (lane & 7)) * WP + k + (((lane >> 3) & 1) << 3));
                    asm volatile(
                        "ldmatrix.sync.aligned.m8n8.x2.shared.b16 {%0,%1},[%2];"
                        : "=r"(b0), "=r"(b1) : "r"(addr));
                }
                uint32_t a0, a1, a2, a3;
                {
                    uint32_t addr = s2u(Hsm + (mt * 16 + (lane & 15)) * WP + k + ((lane >> 4) << 3));
                    asm volatile(
                        "ldmatrix.sync.aligned.m8n8.x4.shared.b16 {%0,%1,%2,%3},[%4];"
                        : "=r"(a0), "=r"(a1), "=r"(a2), "=r"(a3) : "r"(addr));
                }
                asm volatile(
                    "mma.sync.aligned.m16n8k16.row.col.f32.bf16.bf16.f32 "
                    "{%0,%1,%2,%3},{%4,%5,%6,%7},{%8,%9},{%0,%1,%2,%3};"
                    : "+f"(acc[0]), "+f"(acc[1]), "+f"(acc[2]), "+f"(acc[3])
                    : "r"(a0), "r"(a1), "r"(a2), "r"(a3), "r"(b0), "r"(b1));
                {
                    uint32_t addr = s2u(Hsm + (32 + mt * 16 + (lane & 15)) * WP + k + ((lane >> 4) << 3));
                    asm volatile(
                        "ldmatrix.sync.aligned.m8n8.x4.shared.b16 {%0,%1,%2,%3},[%4];"
                        : "=r"(a0), "=r"(a1), "=r"(a2), "=r"(a3) : "r"(addr));
                }
                asm volatile(
                    "mma.sync.aligned.m16n8k16.row.col.f32.bf16.bf16.f32 "
                    "{%0,%1,%2,%3},{%4,%5,%6,%7},{%8,%9},{%0,%1,%2,%3};"
                    : "+f"(acc[0]), "+f"(acc[1]), "+f"(acc[2]), "+f"(acc[3])
                    : "r"(a0), "r"(a1), "r"(a2), "r"(a3), "r"(b0), "r"(b1));
            }
        }
#undef STAGE_CHUNK

        // gates + xg -> gsm (warp nw owns gate nw's 8 cols)
        gsm[r0 * 33 + nw * 8 + cc]           = acc[0] + xv01.x;
        gsm[r0 * 33 + nw * 8 + cc + 1]       = acc[1] + xv01.y;
        gsm[(r0 + 8) * 33 + nw * 8 + cc]     = acc[2] + xv23.x;
        gsm[(r0 + 8) * 33 + nw * 8 + cc + 1] = acc[3] + xv23.y;
        __syncthreads();

        // cell: 1 elem/thread (32 batches x 8 h-cols)
        {
            int b = tid >> 3, j = tid & 7;
            float iv = gsm[b * 33 + j];
            float fv = gsm[b * 33 + 8 + j];
            float gv = gsm[b * 33 + 16 + j];
            float ov = gsm[b * 33 + 24 + j];
            float cn = sigm(fv) * csm[tid] + sigm(iv) * tanhf(gv);
            csm[tid] = cn;
            float hv = sigm(ov) * tanhf(cn);
            __nv_bfloat16 hb = __float2bfloat16(hv);
            __nv_bfloat16 lb = __float2bfloat16(hv - __bfloat162float(hb));
            int idx = b * Hz + j0 + j;
            Hhi[(size_t)t * BH + idx] = hb;
            hlo[(size_t)(t & 1) * BH + idx] = lb;
            if (t == Tz - 1) {
                hf_hi[idx] = hb;
                hf_lo[idx] = lb;
                c_final[idx] = cn;
            }
        }
        if (t < Tz - 1) gridbar(phase);   // last step ordered by kernel boundary
    }
}

// ---------------- in-place log_softmax (online 2-pass) ------------------------
__global__ __launch_bounds__(256)
void logsoftmax_k(float* __restrict__ out) {
    float* row = out + (size_t)blockIdx.x * Vz;
    float4* r4 = (float4*)row;
    const int tid = threadIdx.x;
    __shared__ float smx[8], ssm[8];

    float m = -1e30f, s = 0.f;
    for (int i = tid; i < Vz / 4; i += 256) {
        float4 v = r4[i];
        float vv[4] = {v.x, v.y, v.z, v.w};
#pragma unroll
        for (int u = 0; u < 4; u++) {
            float val = vv[u];
            if (val <= m) {
                s += __expf(val - m);
            } else {
                s = s * __expf(m - val) + 1.f;
                m = val;
            }
        }
    }
#pragma unroll
    for (int o = 16; o; o >>= 1) {
        float om = __shfl_xor_sync(~0u, m, o);
        float os = __shfl_xor_sync(~0u, s, o);
        float M = fmaxf(m, om);
        s = s * __expf(m - M) + os * __expf(om - M);
        m = M;
    }
    if ((tid & 31) == 0) { smx[tid >> 5] = m; ssm[tid >> 5] = s; }
    __syncthreads();
    if (tid < 32) {
        float mm = (tid < 8) ? smx[tid] : -1e30f;
        float sv = (tid < 8) ? ssm[tid] : 0.f;
#pragma unroll
        for (int o = 4; o; o >>= 1) {
            float om = __shfl_xor_sync(~0u, mm, o);
            float os = __shfl_xor_sync(~0u, sv, o);
            float M = fmaxf(mm, om);
            sv = sv * __expf(mm - M) + os * __expf(om - M);
            mm = M;
        }
        if (tid == 0) { smx[0] = mm; ssm[0] = sv; }
    }
    __syncthreads();
    float lse = smx[0] + logf(ssm[0]);

    for (int i = tid; i < Vz / 4; i += 256) {
        float4 v = r4[i];
        v.x -= lse; v.y -= lse; v.z -= lse; v.w -= lse;
        r4[i] = v;
    }
}

// ---------------- driver ------------------------------------------------------
extern "C" void kernel_launch(void* const* d_in, const int* in_sizes, int n_in,
                              void* d_out, int out_size) {
    const int*   x     = (const int*)d_in[0];
    const int*   tgt   = (const int*)d_in[1];
    const float* emb   = (const float*)d_in[2];
    const float* eWih0 = (const float*)d_in[3];
    const float* eWhh0 = (const float*)d_in[4];
    const float* eb0   = (const float*)d_in[5];
    const float* eWih1 = (const float*)d_in[6];
    const float* eWhh1 = (const float*)d_in[7];
    const float* eb1   = (const float*)d_in[8];
    const float* dWih0 = (const float*)d_in[9];
    const float* dWhh0 = (const float*)d_in[10];
    const float* db0   = (const float*)d_in[11];
    const float* dWih1 = (const float*)d_in[12];
    const float* dWhh1 = (const float*)d_in[13];
    const float* db1   = (const float*)d_in[14];
    const float* fcW   = (const float*)d_in[15];
    const float* fcb   = (const float*)d_in[16];
    float* out = (float*)d_out;

    float *xg, *zc, *cf0, *cf1, *dc;
    __nv_bfloat16 *Wbf, *Whhbf, *Hbf0, *Hbf1, *Abf, *hlo, *zbf;
    __nv_bfloat16 *hf0hi, *hf0lo, *hf1hi, *hf1lo, *dhfhi, *dhflo;
    cudaGetSymbolAddress((void**)&xg,    g_xg);
    cudaGetSymbolAddress((void**)&Wbf,   g_Wbf);
    cudaGetSymbolAddress((void**)&Whhbf, g_Whhbf);
    cudaGetSymbolAddress((void**)&Hbf0,  g_Hbf0);
    cudaGetSymbolAddress((void**)&Hbf1,  g_Hbf1);
    cudaGetSymbolAddress((void**)&Abf,   g_Abf);
    cudaGetSymbolAddress((void**)&hlo,   g_hlo);
    cudaGetSymbolAddress((void**)&zbf,   g_zbf);
    cudaGetSymbolAddress((void**)&zc,    g_zc);
    cudaGetSymbolAddress((void**)&hf0hi, g_hf0hi);
    cudaGetSymbolAddress((void**)&hf0lo, g_hf0lo);
    cudaGetSymbolAddress((void**)&hf1hi, g_hf1hi);
    cudaGetSymbolAddress((void**)&hf1lo, g_hf1lo);
    cudaGetSymbolAddress((void**)&cf0,   g_cf0);
    cudaGetSymbolAddress((void**)&cf1,   g_cf1);
    cudaGetSymbolAddress((void**)&dhfhi, g_dhfhi);
    cudaGetSymbolAddress((void**)&dhflo, g_dhflo);
    cudaGetSymbolAddress((void**)&dc,    g_dc);

    cudaFuncSetAttribute(lstm_layer, cudaFuncAttributeMaxDynamicSharedMemorySize, LSTM_SMEM);

    dim3 gGate(Gz / 128, TB / 128);
    dim3 gFC(Vz / 128, TB / 128);
    auto cgrid = [](int n) { return (n / 4 + 255) / 256; };

    zero_k<<<BH / 256, 256>>>(zc, BH);
    zero_k<<<(BH / 2) / 256, 256>>>((float*)zbf, BH / 2);

    // ---------- encoder layer 0 ----------
    embed_enc<<<TB, 128>>>(x, emb, Abf);
    f2bf<<<cgrid(Gz * Ez), 256>>>(Wbf, eWih0, Gz * Ez);
    bgemm<0><<<gGate, 256>>>(Abf, Wbf, eb0, xg, TB, Gz, Ez);
    f2bf<<<cgrid(Gz * Hz), 256>>>(Whhbf, eWhh0, Gz * Hz);
    lstm_layer<<<128, 256, LSTM_SMEM>>>(xg, Whhbf, zbf, zbf, zc, Hbf0, hlo,
                                        hf0hi, hf0lo, cf0);

    // ---------- encoder layer 1 ----------
    f2bf<<<cgrid(Gz * Hz), 256>>>(Wbf, eWih1, Gz * Hz);
    bgemm<0><<<gGate, 256>>>(Hbf0, Wbf, eb1, xg, TB, Gz, Hz);
    f2bf<<<cgrid(Gz * Hz), 256>>>(Whhbf, eWhh1, Gz * Hz);
    lstm_layer<<<128, 256, LSTM_SMEM>>>(xg, Whhbf, zbf, zbf, zc, Hbf1, hlo,
                                        hf1hi, hf1lo, cf1);

    // ---------- decoder layer 0 (init = enc layer0 finals) ----------
    embed_dec<<<TB, 128>>>(tgt, emb, Abf);
    f2bf<<<cgrid(Gz * Ez), 256>>>(Wbf, dWih0, Gz * Ez);
    bgemm<0><<<gGate, 256>>>(Abf, Wbf, db0, xg, TB, Gz, Ez);
    f2bf<<<cgrid(Gz * Hz), 256>>>(Whhbf, dWhh0, Gz * Hz);
    lstm_layer<<<128, 256, LSTM_SMEM>>>(xg, Whhbf, hf0hi, hf0lo, cf0, Hbf0, hlo,
                                        dhfhi, dhflo, dc);

    // ---------- decoder layer 1 (init = enc layer1 finals) ----------
    f2bf<<<cgrid(Gz * Hz), 256>>>(Wbf, dWih1, Gz * Hz);
    bgemm<0><<<gGate, 256>>>(Hbf0, Wbf, db1, xg, TB, Gz, Hz);
    f2bf<<<cgrid(Gz * Hz), 256>>>(Whhbf, dWhh1, Gz * Hz);
    lstm_layer<<<128, 256, LSTM_SMEM>>>(xg, Whhbf, hf1hi, hf1lo, cf1, Hbf1, hlo,
                                        dhfhi, dhflo, dc);

    // ---------- FC projection (fused b,t remap) + log_softmax ----------
    f2bf<<<cgrid(Vz * Hz), 256>>>(Wbf, fcW, Vz * Hz);
    bgemm<1><<<gFC, 256>>>(Hbf1, Wbf, fcb, out, TB, Vz, Hz);
    logsoftmax_k<<<TB, 256>>>(out);
}

// round 14
// speedup vs baseline: 5.4807x; 1.1790x over previous
#include <cuda_runtime.h>
#include <cuda_bf16.h>
#include <math.h>
#include <stdint.h>

#define Bz 32
#define Tz 128
#define Ez 512
#define Hz 1024
#define Gz 4096   // 4*H
#define Vz 32000
#define TB 4096   // T*B
#define BH (Bz * Hz)
#define PITCH 40  // bgemm smem pitch
#define WP 1032   // lstm smem pitch (bf16 elems)

// ---------------- scratch (static device globals; no allocs allowed) ----------
__device__ float g_xg[(size_t)TB * Gz];               // 64 MB fp32 input gates
__device__ __nv_bfloat16 g_Wbf[(size_t)Vz * Hz];      // 64 MB bf16 GEMM weights
__device__ __nv_bfloat16 g_Whhbf[(size_t)Gz * Hz];    // 8 MB bf16 recurrent W
__device__ __nv_bfloat16 g_Hbf0[(size_t)TB * Hz];     // 8 MB h sequence
__device__ __nv_bfloat16 g_Hbf1[(size_t)TB * Hz];     // 8 MB h sequence
__device__ __nv_bfloat16 g_Abf[(size_t)TB * Ez];      // 4 MB embed bf16
__device__ __nv_bfloat16 g_zbf[BH];                   // zero bf16 h0
__device__ float g_zc[BH];                            // zero fp32 c0
__device__ __nv_bfloat16 g_hf0[BH], g_hf1[BH];
__device__ float g_cf0[BH], g_cf1[BH];
__device__ __nv_bfloat16 g_dhf[BH];
__device__ float g_dc[BH];
__device__ unsigned g_cnt[8 * 32];   // bucket counters, 128B apart
__device__ unsigned g_root;
__device__ unsigned g_barphase;

// ---------------- small helpers ----------------------------------------------
__global__ void zero_k(float* p, int n) {
    int i = blockIdx.x * blockDim.x + threadIdx.x;
    if (i < n) p[i] = 0.f;
}
__global__ void f2bf(__nv_bfloat16* __restrict__ d, const float* __restrict__ s, int n) {
    int i = (blockIdx.x * blockDim.x + threadIdx.x) * 4;
    if (i < n) {
        float4 v = *(const float4*)(s + i);
        __nv_bfloat162 lo = __floats2bfloat162_rn(v.x, v.y);
        __nv_bfloat162 hi = __floats2bfloat162_rn(v.z, v.w);
        uint2 pk;
        pk.x = *(uint32_t*)&lo;
        pk.y = *(uint32_t*)&hi;
        *(uint2*)(d + i) = pk;
    }
}
__device__ __forceinline__ uint32_t s2u(const void* p) {
    return (uint32_t)__cvta_generic_to_shared(p);
}
__device__ __forceinline__ void cp16(void* dst, const void* src) {
    uint32_t d = s2u(dst);
    asm volatile("cp.async.cg.shared.global [%0], [%1], 16;" :: "r"(d), "l"(src));
}
#define CP_COMMIT asm volatile("cp.async.commit_group;" ::: "memory")
#define CP_WAIT0  asm volatile("cp.async.wait_group 0;" ::: "memory")
#define CP_WAIT1  asm volatile("cp.async.wait_group 1;" ::: "memory")
__device__ __forceinline__ float sigm(float x) { return 1.f / (1.f + expf(-x)); }

// ---------------- embedding gathers -> bf16 [T,B,E] ---------------------------
__global__ void embed_enc(const int* __restrict__ x, const float* __restrict__ emb,
                          __nv_bfloat16* __restrict__ out) {
    int tb = blockIdx.x;
    int t = tb >> 5, b = tb & 31;
    int tok = x[b * Tz + t];
    float4 v = ((const float4*)(emb + (size_t)tok * Ez))[threadIdx.x];
    __nv_bfloat162 lo = __floats2bfloat162_rn(v.x, v.y);
    __nv_bfloat162 hi = __floats2bfloat162_rn(v.z, v.w);
    uint2 pk; pk.x = *(uint32_t*)&lo; pk.y = *(uint32_t*)&hi;
    *(uint2*)(out + (size_t)tb * Ez + threadIdx.x * 4) = pk;
}
__global__ void embed_dec(const int* __restrict__ tgt, const float* __restrict__ emb,
                          __nv_bfloat16* __restrict__ out) {
    int tb = blockIdx.x;
    int t = tb >> 5, b = tb & 31;
    int tok = (t == 0) ? 0 : tgt[b * Tz + t - 1];
    float4 v = ((const float4*)(emb + (size_t)tok * Ez))[threadIdx.x];
    __nv_bfloat162 lo = __floats2bfloat162_rn(v.x, v.y);
    __nv_bfloat162 hi = __floats2bfloat162_rn(v.z, v.w);
    uint2 pk; pk.x = *(uint32_t*)&lo; pk.y = *(uint32_t*)&hi;
    *(uint2*)(out + (size_t)tb * Ez + threadIdx.x * 4) = pk;
}

// ---------------- bf16 tensor-core GEMM, cp.async double-buffered -------------
__device__ __forceinline__ void bg_load(int tid, __nv_bfloat16* As, __nv_bfloat16* Ws,
                                        const __nv_bfloat16* A, const __nv_bfloat16* W,
                                        int m0, int n0, int K, int k0) {
#pragma unroll
    for (int s = 0; s < 2; s++) {
        int c = tid + s * 256;
        int row = c >> 2, seg = c & 3;
        cp16(As + row * PITCH + seg * 8, A + (size_t)(m0 + row) * K + k0 + seg * 8);
        cp16(Ws + row * PITCH + seg * 8, W + (size_t)(n0 + row) * K + k0 + seg * 8);
    }
    CP_COMMIT;
}

template <int REMAP>
__global__ __launch_bounds__(256)
void bgemm(const __nv_bfloat16* __restrict__ A, const __nv_bfloat16* __restrict__ W,
           const float* __restrict__ bias, float* __restrict__ C,
           int M, int N, int K) {
    __shared__ __nv_bfloat16 As[2][128 * PITCH];
    __shared__ __nv_bfloat16 Ws[2][128 * PITCH];

    int tid = threadIdx.x;
    int wid = tid >> 5, lane = tid & 31;
    int wm = wid >> 2;
    int wn = wid & 3;
    int m0 = blockIdx.y * 128;
    int n0 = blockIdx.x * 128;

    float acc[4][4][4];
#pragma unroll
    for (int a = 0; a < 4; a++)
#pragma unroll
        for (int b = 0; b < 4; b++)
#pragma unroll
            for (int cidx = 0; cidx < 4; cidx++) acc[a][b][cidx] = 0.f;

    bg_load(tid, As[0], Ws[0], A, W, m0, n0, K, 0);
    const int KT = K >> 5;

    for (int kt = 0; kt < KT; kt++) {
        CP_WAIT0;
        __syncthreads();
        if (kt + 1 < KT)
            bg_load(tid, As[(kt + 1) & 1], Ws[(kt + 1) & 1], A, W, m0, n0, K, (kt + 1) * 32);
        const __nv_bfloat16* Ab = As[kt & 1];
        const __nv_bfloat16* Wb = Ws[kt & 1];

#pragma unroll
        for (int ks = 0; ks < 32; ks += 16) {
            uint32_t afr[4][4];
            uint32_t bfr[4][2];
#pragma unroll
            for (int mt = 0; mt < 4; mt++) {
                int row = wm * 64 + mt * 16 + (lane & 15);
                int col = ks + ((lane >> 4) << 3);
                uint32_t addr = s2u(Ab + row * PITCH + col);
                asm volatile(
                    "ldmatrix.sync.aligned.m8n8.x4.shared.b16 {%0,%1,%2,%3},[%4];"
                    : "=r"(afr[mt][0]), "=r"(afr[mt][1]), "=r"(afr[mt][2]), "=r"(afr[mt][3])
                    : "r"(addr));
            }
#pragma unroll
            for (int nt = 0; nt < 4; nt++) {
                int row = wn * 32 + nt * 8 + (lane & 7);
                int col = ks + (((lane >> 3) & 1) << 3);
                uint32_t addr = s2u(Wb + row * PITCH + col);
                asm volatile(
                    "ldmatrix.sync.aligned.m8n8.x2.shared.b16 {%0,%1},[%2];"
                    : "=r"(bfr[nt][0]), "=r"(bfr[nt][1])
                    : "r"(addr));
            }
#pragma unroll
            for (int mt = 0; mt < 4; mt++)
#pragma unroll
                for (int nt = 0; nt < 4; nt++) {
                    asm volatile(
                        "mma.sync.aligned.m16n8k16.row.col.f32.bf16.bf16.f32 "
                        "{%0,%1,%2,%3},{%4,%5,%6,%7},{%8,%9},{%0,%1,%2,%3};"
                        : "+f"(acc[mt][nt][0]), "+f"(acc[mt][nt][1]),
                          "+f"(acc[mt][nt][2]), "+f"(acc[mt][nt][3])
                        : "r"(afr[mt][0]), "r"(afr[mt][1]), "r"(afr[mt][2]), "r"(afr[mt][3]),
                          "r"(bfr[nt][0]), "r"(bfr[nt][1]));
                }
        }
    }

#pragma unroll
    for (int mt = 0; mt < 4; mt++) {
#pragma unroll
        for (int nt = 0; nt < 4; nt++) {
            int col = n0 + wn * 32 + nt * 8 + (lane & 3) * 2;
            float b0 = bias[col], b1 = bias[col + 1];
#pragma unroll
            for (int half = 0; half < 2; half++) {
                int m = m0 + wm * 64 + mt * 16 + (lane >> 2) + half * 8;
                float2 v;
                v.x = acc[mt][nt][half * 2 + 0] + b0;
                v.y = acc[mt][nt][half * 2 + 1] + b1;
                if (REMAP) {
                    int b = m & 31, t = m >> 5;
                    *(float2*)(C + ((size_t)b * Tz + t) * Vz + col) = v;
                } else {
                    *(float2*)(C + (size_t)m * N + col) = v;
                }
            }
        }
    }
}

// ---------------- persistent LSTM layer (bf16 h, no lo path) ------------------
#define OFF_W 0
#define OFF_H (OFF_W + 32 * WP * 2)
#define OFF_G (OFF_H + 32 * WP * 2)
#define OFF_C (OFF_G + 32 * 33 * 4)
#define LSTM_SMEM (OFF_C + 256 * 4)

__device__ __forceinline__ void gridbar(unsigned& phase) {
    __threadfence();
    __syncthreads();
    if (threadIdx.x == 0) {
        unsigned tgt = phase + 1;
        int bkt = (blockIdx.x & 7) * 32;
        if (atomicAdd(&g_cnt[bkt], 1) == 15) {
            atomicExch(&g_cnt[bkt], 0);
            if (atomicAdd(&g_root, 1) == 7) {
                atomicExch(&g_root, 0);
                __threadfence();
                atomicExch(&g_barphase, tgt);
            }
        }
        while (*(volatile unsigned*)&g_barphase != tgt) { }
        phase = tgt;
    }
    __syncthreads();
}

__global__ __launch_bounds__(256, 1)
void lstm_layer(const float* __restrict__ xg,
                const __nv_bfloat16* __restrict__ Wbf,
                const __nv_bfloat16* __restrict__ h0,
                const float* __restrict__ c_init,
                __nv_bfloat16* __restrict__ Hseq,
                __nv_bfloat16* __restrict__ hf,
                float* __restrict__ c_final) {
    extern __shared__ char smem[];
    __nv_bfloat16* Wsm = (__nv_bfloat16*)(smem + OFF_W);   // [32][WP]
    __nv_bfloat16* Hsm = (__nv_bfloat16*)(smem + OFF_H);   // [32][WP]
    float* gsm = (float*)(smem + OFF_G);                   // [32][33]
    float* csm = (float*)(smem + OFF_C);                   // [256]

    const int tid = threadIdx.x;
    const int wid = tid >> 5, lane = tid & 31;
    const int mt = wid >> 2;          // batch half (rows mt*16..+16)
    const int nw = wid & 3;           // gate index (8 cols each)
    const int j0 = blockIdx.x * 8;

    // one-time: W slice (32 gate cols x 1024 K) into smem
#pragma unroll
    for (int u = 0; u < 16; u++) {
        int c = tid + 256 * u;
        int r = c >> 7, seg = c & 127;
        int grow = (r >> 3) * Hz + j0 + (r & 7);
        uint4 v = *(const uint4*)(Wbf + (size_t)grow * Hz + seg * 8);
        *(uint4*)(Wsm + r * WP + seg * 8) = v;
    }
    {
        int b = tid >> 3, j = tid & 7;
        csm[tid] = c_init[b * Hz + j0 + j];
    }
    unsigned phase = 0;
    if (tid == 0) phase = *(volatile unsigned*)&g_barphase;
    __syncthreads();

    // per-thread output coordinates (warp computes one 16x8 gate tile)
    const int r0 = mt * 16 + (lane >> 2);        // batch row
    const int cc = (lane & 3) * 2;               // col pair within gate

    for (int t = 0; t < Tz; t++) {
        const __nv_bfloat16* sh = (t == 0) ? h0 : (Hseq + (size_t)(t - 1) * BH);

        // prefetch xg for this thread's 4 output gates
        const float* xp = xg + ((size_t)t * Bz + r0) * Gz + nw * Hz + j0 + cc;
        float2 xv01 = *(const float2*)xp;
        float2 xv23 = *(const float2*)(xp + 8 * Gz);

        // chunked cp.async staging of h (chunk = 256 K-cols, 4 cp16/thread)
#define STAGE_CHUNK(CK) do {                                               \
        int kc_ = (CK) * 256;                                              \
        _Pragma("unroll")                                                  \
        for (int u = 0; u < 4; u++) {                                      \
            int c_ = tid + 256 * u;                                        \
            int r_ = c_ >> 5, sg_ = c_ & 31;                               \
            cp16(Hsm + r_ * WP + kc_ + sg_ * 8,                            \
                 sh + (size_t)r_ * Hz + kc_ + sg_ * 8);                    \
        }                                                                  \
        CP_COMMIT; } while (0)

        STAGE_CHUNK(0);

        float acc[4] = {0.f, 0.f, 0.f, 0.f};

        for (int ck = 0; ck < 4; ck++) {
            if (ck + 1 < 4) STAGE_CHUNK(ck + 1);
            if (ck + 1 < 4) { CP_WAIT1; } else { CP_WAIT0; }
            __syncthreads();
            int kc = ck * 256;
#pragma unroll
            for (int ki = 0; ki < 16; ki++) {
                int k = kc + (ki << 4);
                uint32_t b0, b1;
                {
                    uint32_t addr = s2u(Wsm + (nw * 8 + (lane & 7)) * WP + k + (((lane >> 3) & 1) << 3));
                    asm volatile(
                        "ldmatrix.sync.aligned.m8n8.x2.shared.b16 {%0,%1},[%2];"
                        : "=r"(b0), "=r"(b1) : "r"(addr));
                }
                uint32_t a0, a1, a2, a3;
                {
                    uint32_t addr = s2u(Hsm + (mt * 16 + (lane & 15)) * WP + k + ((lane >> 4) << 3));
                    asm volatile(
                        "ldmatrix.sync.aligned.m8n8.x4.shared.b16 {%0,%1,%2,%3},[%4];"
                        : "=r"(a0), "=r"(a1), "=r"(a2), "=r"(a3) : "r"(addr));
                }
                asm volatile(
                    "mma.sync.aligned.m16n8k16.row.col.f32.bf16.bf16.f32 "
                    "{%0,%1,%2,%3},{%4,%5,%6,%7},{%8,%9},{%0,%1,%2,%3};"
                    : "+f"(acc[0]), "+f"(acc[1]), "+f"(acc[2]), "+f"(acc[3])
                    : "r"(a0), "r"(a1), "r"(a2), "r"(a3), "r"(b0), "r"(b1));
            }
        }
#undef STAGE_CHUNK

        // gates + xg -> gsm (warp nw owns gate nw's 8 cols)
        gsm[r0 * 33 + nw * 8 + cc]           = acc[0] + xv01.x;
        gsm[r0 * 33 + nw * 8 + cc + 1]       = acc[1] + xv01.y;
        gsm[(r0 + 8) * 33 + nw * 8 + cc]     = acc[2] + xv23.x;
        gsm[(r0 + 8) * 33 + nw * 8 + cc + 1] = acc[3] + xv23.y;
        __syncthreads();

        // cell: 1 elem/thread (32 batches x 8 h-cols)
        {
            int b = tid >> 3, j = tid & 7;
            float iv = gsm[b * 33 + j];
            float fv = gsm[b * 33 + 8 + j];
            float gv = gsm[b * 33 + 16 + j];
            float ov = gsm[b * 33 + 24 + j];
            float cn = sigm(fv) * csm[tid] + sigm(iv) * tanhf(gv);
            csm[tid] = cn;
            float hv = sigm(ov) * tanhf(cn);
            __nv_bfloat16 hb = __float2bfloat16(hv);
            int idx = b * Hz + j0 + j;
            Hseq[(size_t)t * BH + idx] = hb;
            if (t == Tz - 1) {
                hf[idx] = hb;
                c_final[idx] = cn;
            }
        }
        if (t < Tz - 1) gridbar(phase);   // last step ordered by kernel boundary
    }
}

// ---------------- in-place log_softmax (online 2-pass) ------------------------
__global__ __launch_bounds__(256)
void logsoftmax_k(float* __restrict__ out) {
    float* row = out + (size_t)blockIdx.x * Vz;
    float4* r4 = (float4*)row;
    const int tid = threadIdx.x;
    __shared__ float smx[8], ssm[8];

    float m = -1e30f, s = 0.f;
    for (int i = tid; i < Vz / 4; i += 256) {
        float4 v = r4[i];
        float vv[4] = {v.x, v.y, v.z, v.w};
#pragma unroll
        for (int u = 0; u < 4; u++) {
            float val = vv[u];
            if (val <= m) {
                s += __expf(val - m);
            } else {
                s = s * __expf(m - val) + 1.f;
                m = val;
            }
        }
    }
#pragma unroll
    for (int o = 16; o; o >>= 1) {
        float om = __shfl_xor_sync(~0u, m, o);
        float os = __shfl_xor_sync(~0u, s, o);
        float M = fmaxf(m, om);
        s = s * __expf(m - M) + os * __expf(om - M);
        m = M;
    }
    if ((tid & 31) == 0) { smx[tid >> 5] = m; ssm[tid >> 5] = s; }
    __syncthreads();
    if (tid < 32) {
        float mm = (tid < 8) ? smx[tid] : -1e30f;
        float sv = (tid < 8) ? ssm[tid] : 0.f;
#pragma unroll
        for (int o = 4; o; o >>= 1) {
            float om = __shfl_xor_sync(~0u, mm, o);
            float os = __shfl_xor_sync(~0u, sv, o);
            float M = fmaxf(mm, om);
            sv = sv * __expf(mm - M) + os * __expf(om - M);
            mm = M;
        }
        if (tid == 0) { smx[0] = mm; ssm[0] = sv; }
    }
    __syncthreads();
    float lse = smx[0] + logf(ssm[0]);

    for (int i = tid; i < Vz / 4; i += 256) {
        float4 v = r4[i];
        v.x -= lse; v.y -= lse; v.z -= lse; v.w -= lse;
        r4[i] = v;
    }
}

// ---------------- driver ------------------------------------------------------
extern "C" void kernel_launch(void* const* d_in, const int* in_sizes, int n_in,
                              void* d_out, int out_size) {
    const int*   x     = (const int*)d_in[0];
    const int*   tgt   = (const int*)d_in[1];
    const float* emb   = (const float*)d_in[2];
    const float* eWih0 = (const float*)d_in[3];
    const float* eWhh0 = (const float*)d_in[4];
    const float* eb0   = (const float*)d_in[5];
    const float* eWih1 = (const float*)d_in[6];
    const float* eWhh1 = (const float*)d_in[7];
    const float* eb1   = (const float*)d_in[8];
    const float* dWih0 = (const float*)d_in[9];
    const float* dWhh0 = (const float*)d_in[10];
    const float* db0   = (const float*)d_in[11];
    const float* dWih1 = (const float*)d_in[12];
    const float* dWhh1 = (const float*)d_in[13];
    const float* db1   = (const float*)d_in[14];
    const float* fcW   = (const float*)d_in[15];
    const float* fcb   = (const float*)d_in[16];
    float* out = (float*)d_out;

    float *xg, *zc, *cf0, *cf1, *dc;
    __nv_bfloat16 *Wbf, *Whhbf, *Hbf0, *Hbf1, *Abf, *zbf;
    __nv_bfloat16 *hf0, *hf1, *dhf;
    cudaGetSymbolAddress((void**)&xg,    g_xg);
    cudaGetSymbolAddress((void**)&Wbf,   g_Wbf);
    cudaGetSymbolAddress((void**)&Whhbf, g_Whhbf);
    cudaGetSymbolAddress((void**)&Hbf0,  g_Hbf0);
    cudaGetSymbolAddress((void**)&Hbf1,  g_Hbf1);
    cudaGetSymbolAddress((void**)&Abf,   g_Abf);
    cudaGetSymbolAddress((void**)&zbf,   g_zbf);
    cudaGetSymbolAddress((void**)&zc,    g_zc);
    cudaGetSymbolAddress((void**)&hf0,   g_hf0);
    cudaGetSymbolAddress((void**)&hf1,   g_hf1);
    cudaGetSymbolAddress((void**)&cf0,   g_cf0);
    cudaGetSymbolAddress((void**)&cf1,   g_cf1);
    cudaGetSymbolAddress((void**)&dhf,   g_dhf);
    cudaGetSymbolAddress((void**)&dc,    g_dc);

    cudaFuncSetAttribute(lstm_layer, cudaFuncAttributeMaxDynamicSharedMemorySize, LSTM_SMEM);

    dim3 gGate(Gz / 128, TB / 128);
    dim3 gFC(Vz / 128, TB / 128);
    auto cgrid = [](int n) { return (n / 4 + 255) / 256; };

    zero_k<<<BH / 256, 256>>>(zc, BH);
    zero_k<<<(BH / 2) / 256, 256>>>((float*)zbf, BH / 2);

    // ---------- encoder layer 0 ----------
    embed_enc<<<TB, 128>>>(x, emb, Abf);
    f2bf<<<cgrid(Gz * Ez), 256>>>(Wbf, eWih0, Gz * Ez);
    bgemm<0><<<gGate, 256>>>(Abf, Wbf, eb0, xg, TB, Gz, Ez);
    f2bf<<<cgrid(Gz * Hz), 256>>>(Whhbf, eWhh0, Gz * Hz);
    lstm_layer<<<128, 256, LSTM_SMEM>>>(xg, Whhbf, zbf, zc, Hbf0, hf0, cf0);

    // ---------- encoder layer 1 ----------
    f2bf<<<cgrid(Gz * Hz), 256>>>(Wbf, eWih1, Gz * Hz);
    bgemm<0><<<gGate, 256>>>(Hbf0, Wbf, eb1, xg, TB, Gz, Hz);
    f2bf<<<cgrid(Gz * Hz), 256>>>(Whhbf, eWhh1, Gz * Hz);
    lstm_layer<<<128, 256, LSTM_SMEM>>>(xg, Whhbf, zbf, zc, Hbf1, hf1, cf1);

    // ---------- decoder layer 0 (init = enc layer0 finals) ----------
    embed_dec<<<TB, 128>>>(tgt, emb, Abf);
    f2bf<<<cgrid(Gz * Ez), 256>>>(Wbf, dWih0, Gz * Ez);
    bgemm<0><<<gGate, 256>>>(Abf, Wbf, db0, xg, TB, Gz, Ez);
    f2bf<<<cgrid(Gz * Hz), 256>>>(Whhbf, dWhh0, Gz * Hz);
    lstm_layer<<<128, 256, LSTM_SMEM>>>(xg, Whhbf, hf0, cf0, Hbf0, dhf, dc);

    // ---------- decoder layer 1 (init = enc layer1 finals) ----------
    f2bf<<<cgrid(Gz * Hz), 256>>>(Wbf, dWih1, Gz * Hz);
    bgemm<0><<<gGate, 256>>>(Hbf0, Wbf, db1, xg, TB, Gz, Hz);
    f2bf<<<cgrid(Gz * Hz), 256>>>(Whhbf, dWhh1, Gz * Hz);
    lstm_layer<<<128, 256, LSTM_SMEM>>>(xg, Whhbf, hf1, cf1, Hbf1, dhf, dc);

    // ---------- FC projection (fused b,t remap) + log_softmax ----------
    f2bf<<<cgrid(Vz * Hz), 256>>>(Wbf, fcW, Vz * Hz);
    bgemm<1><<<gFC, 256>>>(Hbf1, Wbf, fcb, out, TB, Vz, Hz);
    logsoftmax_k<<<TB, 256>>>(out);
}

// round 15
// speedup vs baseline: 5.6230x; 1.0260x over previous
#include <cuda_runtime.h>
#include <cuda_bf16.h>
#include <math.h>
#include <stdint.h>

#define Bz 32
#define Tz 128
#define Ez 512
#define Hz 1024
#define Gz 4096   // 4*H
#define Vz 32000
#define TB 4096   // T*B
#define BH (Bz * Hz)
#define PITCH 40  // bgemm smem pitch
#define WP 1032   // lstm smem pitch (bf16 elems)

// ---------------- scratch (static device globals; no allocs allowed) ----------
__device__ float g_xg[(size_t)TB * Gz];               // 64 MB fp32 input gates
__device__ __nv_bfloat16 g_Wbf[(size_t)Vz * Hz];      // 64 MB bf16 GEMM weights
__device__ __nv_bfloat16 g_Whhbf[(size_t)Gz * Hz];    // 8 MB bf16 recurrent W
__device__ __nv_bfloat16 g_Hbf0[(size_t)TB * Hz];     // 8 MB h sequence
__device__ __nv_bfloat16 g_Hbf1[(size_t)TB * Hz];     // 8 MB h sequence
__device__ __nv_bfloat16 g_Abf[(size_t)TB * Ez];      // 4 MB embed bf16
__device__ __nv_bfloat16 g_zbf[BH];                   // zero bf16 h0
__device__ float g_zc[BH];                            // zero fp32 c0
__device__ __nv_bfloat16 g_hf0[BH], g_hf1[BH];
__device__ float g_cf0[BH], g_cf1[BH];
__device__ __nv_bfloat16 g_dhf[BH];
__device__ float g_dc[BH];
__device__ unsigned g_cnt[8 * 32];   // bucket counters, 128B apart
__device__ unsigned g_root;
__device__ unsigned g_barphase;

// ---------------- small helpers ----------------------------------------------
__global__ void zero_k(float* p, int n) {
    int i = blockIdx.x * blockDim.x + threadIdx.x;
    if (i < n) p[i] = 0.f;
}
__global__ void f2bf(__nv_bfloat16* __restrict__ d, const float* __restrict__ s, int n) {
    int i = (blockIdx.x * blockDim.x + threadIdx.x) * 4;
    if (i < n) {
        float4 v = *(const float4*)(s + i);
        __nv_bfloat162 lo = __floats2bfloat162_rn(v.x, v.y);
        __nv_bfloat162 hi = __floats2bfloat162_rn(v.z, v.w);
        uint2 pk;
        pk.x = *(uint32_t*)&lo;
        pk.y = *(uint32_t*)&hi;
        *(uint2*)(d + i) = pk;
    }
}
__device__ __forceinline__ uint32_t s2u(const void* p) {
    return (uint32_t)__cvta_generic_to_shared(p);
}
__device__ __forceinline__ void cp16(void* dst, const void* src) {
    uint32_t d = s2u(dst);
    asm volatile("cp.async.cg.shared.global [%0], [%1], 16;" :: "r"(d), "l"(src));
}
#define CP_COMMIT asm volatile("cp.async.commit_group;" ::: "memory")
#define CP_WAIT0  asm volatile("cp.async.wait_group 0;" ::: "memory")
#define CP_WAIT1  asm volatile("cp.async.wait_group 1;" ::: "memory")
__device__ __forceinline__ float sigm(float x) { return 1.f / (1.f + expf(-x)); }

// ---------------- embedding gathers -> bf16 [T,B,E] ---------------------------
__global__ void embed_enc(const int* __restrict__ x, const float* __restrict__ emb,
                          __nv_bfloat16* __restrict__ out) {
    int tb = blockIdx.x;
    int t = tb >> 5, b = tb & 31;
    int tok = x[b * Tz + t];
    float4 v = ((const float4*)(emb + (size_t)tok * Ez))[threadIdx.x];
    __nv_bfloat162 lo = __floats2bfloat162_rn(v.x, v.y);
    __nv_bfloat162 hi = __floats2bfloat162_rn(v.z, v.w);
    uint2 pk; pk.x = *(uint32_t*)&lo; pk.y = *(uint32_t*)&hi;
    *(uint2*)(out + (size_t)tb * Ez + threadIdx.x * 4) = pk;
}
__global__ void embed_dec(const int* __restrict__ tgt, const float* __restrict__ emb,
                          __nv_bfloat16* __restrict__ out) {
    int tb = blockIdx.x;
    int t = tb >> 5, b = tb & 31;
    int tok = (t == 0) ? 0 : tgt[b * Tz + t - 1];
    float4 v = ((const float4*)(emb + (size_t)tok * Ez))[threadIdx.x];
    __nv_bfloat162 lo = __floats2bfloat162_rn(v.x, v.y);
    __nv_bfloat162 hi = __floats2bfloat162_rn(v.z, v.w);
    uint2 pk; pk.x = *(uint32_t*)&lo; pk.y = *(uint32_t*)&hi;
    *(uint2*)(out + (size_t)tb * Ez + threadIdx.x * 4) = pk;
}

// ---------------- bf16 tensor-core GEMM, cp.async double-buffered -------------
__device__ __forceinline__ void bg_load(int tid, __nv_bfloat16* As, __nv_bfloat16* Ws,
                                        const __nv_bfloat16* A, const __nv_bfloat16* W,
                                        int m0, int n0, int K, int k0) {
#pragma unroll
    for (int s = 0; s < 2; s++) {
        int c = tid + s * 256;
        int row = c >> 2, seg = c & 3;
        cp16(As + row * PITCH + seg * 8, A + (size_t)(m0 + row) * K + k0 + seg * 8);
        cp16(Ws + row * PITCH + seg * 8, W + (size_t)(n0 + row) * K + k0 + seg * 8);
    }
    CP_COMMIT;
}

template <int REMAP>
__global__ __launch_bounds__(256)
void bgemm(const __nv_bfloat16* __restrict__ A, const __nv_bfloat16* __restrict__ W,
           const float* __restrict__ bias, float* __restrict__ C,
           int M, int N, int K) {
    __shared__ __nv_bfloat16 As[2][128 * PITCH];
    __shared__ __nv_bfloat16 Ws[2][128 * PITCH];

    int tid = threadIdx.x;
    int wid = tid >> 5, lane = tid & 31;
    int wm = wid >> 2;
    int wn = wid & 3;
    int m0 = blockIdx.y * 128;
    int n0 = blockIdx.x * 128;

    float acc[4][4][4];
#pragma unroll
    for (int a = 0; a < 4; a++)
#pragma unroll
        for (int b = 0; b < 4; b++)
#pragma unroll
            for (int cidx = 0; cidx < 4; cidx++) acc[a][b][cidx] = 0.f;

    bg_load(tid, As[0], Ws[0], A, W, m0, n0, K, 0);
    const int KT = K >> 5;

    for (int kt = 0; kt < KT; kt++) {
        CP_WAIT0;
        __syncthreads();
        if (kt + 1 < KT)
            bg_load(tid, As[(kt + 1) & 1], Ws[(kt + 1) & 1], A, W, m0, n0, K, (kt + 1) * 32);
        const __nv_bfloat16* Ab = As[kt & 1];
        const __nv_bfloat16* Wb = Ws[kt & 1];

#pragma unroll
        for (int ks = 0; ks < 32; ks += 16) {
            uint32_t afr[4][4];
            uint32_t bfr[4][2];
#pragma unroll
            for (int mt = 0; mt < 4; mt++) {
                int row = wm * 64 + mt * 16 + (lane & 15);
                int col = ks + ((lane >> 4) << 3);
                uint32_t addr = s2u(Ab + row * PITCH + col);
                asm volatile(
                    "ldmatrix.sync.aligned.m8n8.x4.shared.b16 {%0,%1,%2,%3},[%4];"
                    : "=r"(afr[mt][0]), "=r"(afr[mt][1]), "=r"(afr[mt][2]), "=r"(afr[mt][3])
                    : "r"(addr));
            }
#pragma unroll
            for (int nt = 0; nt < 4; nt++) {
                int row = wn * 32 + nt * 8 + (lane & 7);
                int col = ks + (((lane >> 3) & 1) << 3);
                uint32_t addr = s2u(Wb + row * PITCH + col);
                asm volatile(
                    "ldmatrix.sync.aligned.m8n8.x2.shared.b16 {%0,%1},[%2];"
                    : "=r"(bfr[nt][0]), "=r"(bfr[nt][1])
                    : "r"(addr));
            }
#pragma unroll
            for (int mt = 0; mt < 4; mt++)
#pragma unroll
                for (int nt = 0; nt < 4; nt++) {
                    asm volatile(
                        "mma.sync.aligned.m16n8k16.row.col.f32.bf16.bf16.f32 "
                        "{%0,%1,%2,%3},{%4,%5,%6,%7},{%8,%9},{%0,%1,%2,%3};"
                        : "+f"(acc[mt][nt][0]), "+f"(acc[mt][nt][1]),
                          "+f"(acc[mt][nt][2]), "+f"(acc[mt][nt][3])
                        : "r"(afr[mt][0]), "r"(afr[mt][1]), "r"(afr[mt][2]), "r"(afr[mt][3]),
                          "r"(bfr[nt][0]), "r"(bfr[nt][1]));
                }
        }
    }

#pragma unroll
    for (int mt = 0; mt < 4; mt++) {
#pragma unroll
        for (int nt = 0; nt < 4; nt++) {
            int col = n0 + wn * 32 + nt * 8 + (lane & 3) * 2;
            float b0 = bias[col], b1 = bias[col + 1];
#pragma unroll
            for (int half = 0; half < 2; half++) {
                int m = m0 + wm * 64 + mt * 16 + (lane >> 2) + half * 8;
                float2 v;
                v.x = acc[mt][nt][half * 2 + 0] + b0;
                v.y = acc[mt][nt][half * 2 + 1] + b1;
                if (REMAP) {
                    int b = m & 31, t = m >> 5;
                    *(float2*)(C + ((size_t)b * Tz + t) * Vz + col) = v;
                } else {
                    *(float2*)(C + (size_t)m * N + col) = v;
                }
            }
        }
    }
}

// ---------------- persistent LSTM layer ---------------------------------------
// Gate-interleaved W ordering: warp nw's 8 MMA cols = gates{i,f,g,o} x 2 h-cols.
// W fragments cached in registers (time-invariant). Cell via shfl, c in regs.
#define OFF_W 0
#define OFF_H (OFF_W + 32 * WP * 2)
#define LSTM_SMEM (OFF_H + 32 * WP * 2)

__device__ __forceinline__ void gridbar(unsigned& phase) {
    __threadfence();
    __syncthreads();
    if (threadIdx.x == 0) {
        unsigned tgt = phase + 1;
        int bkt = (blockIdx.x & 7) * 32;
        if (atomicAdd(&g_cnt[bkt], 1) == 15) {
            atomicExch(&g_cnt[bkt], 0);
            if (atomicAdd(&g_root, 1) == 7) {
                atomicExch(&g_root, 0);
                __threadfence();
                atomicExch(&g_barphase, tgt);
            }
        }
        while (*(volatile unsigned*)&g_barphase != tgt) { }
        phase = tgt;
    }
    __syncthreads();
}

__global__ __launch_bounds__(256, 1)
void lstm_layer(const float* __restrict__ xg,
                const __nv_bfloat16* __restrict__ Wbf,
                const __nv_bfloat16* __restrict__ h0,
                const float* __restrict__ c_init,
                __nv_bfloat16* __restrict__ Hseq,
                __nv_bfloat16* __restrict__ hf,
                float* __restrict__ c_final) {
    extern __shared__ char smem[];
    __nv_bfloat16* Wsm = (__nv_bfloat16*)(smem + OFF_W);   // [32][WP]
    __nv_bfloat16* Hsm = (__nv_bfloat16*)(smem + OFF_H);   // [32][WP]

    const int tid = threadIdx.x;
    const int wid = tid >> 5, lane = tid & 31;
    const int mt = wid >> 2;          // batch half (rows mt*16..+16)
    const int nw = wid & 3;           // 2-h-col group
    const int j0 = blockIdx.x * 8;

    // one-time: W slice into smem, gate-interleaved row order:
    // Wsm row r: nw_=r>>3, cidx=r&7 -> gate=cidx&3, jl=nw_*2+(cidx>>2)
#pragma unroll
    for (int u = 0; u < 16; u++) {
        int c = tid + 256 * u;
        int r = c >> 7, seg = c & 127;
        int nw_ = r >> 3, cidx = r & 7;
        int grow = (cidx & 3) * Hz + j0 + nw_ * 2 + (cidx >> 2);
        uint4 v = *(const uint4*)(Wbf + (size_t)grow * Hz + seg * 8);
        *(uint4*)(Wsm + r * WP + seg * 8) = v;
    }
    unsigned phase = 0;
    if (tid == 0) phase = *(volatile unsigned*)&g_barphase;
    __syncthreads();

    // cache W fragments in registers (64 k-steps x 2 regs)
    uint32_t wr0[64], wr1[64];
    {
        uint32_t base = s2u(Wsm + (nw * 8 + (lane & 7)) * WP + (((lane >> 3) & 1) << 3));
#pragma unroll
        for (int kk = 0; kk < 64; kk++) {
            asm volatile("ldmatrix.sync.aligned.m8n8.x2.shared.b16 {%0,%1},[%2];"
                         : "=r"(wr0[kk]), "=r"(wr1[kk]) : "r"(base + kk * 32));
        }
    }

    // per-thread coordinates
    const int r0 = mt * 16 + (lane >> 2);             // mma row (batch)
    const int c0 = (lane & 3) * 2;                    // mma col pair base
    const int g0 = c0 & 3, g1 = (c0 + 1) & 3;         // gates of the pair
    const int jcol = j0 + nw * 2 + (c0 >> 2);         // h-col of the pair
    const int crow = r0 + ((lane & 1) << 3);          // this thread's cell row
    const int cj = jcol;                              // this thread's cell col
    float creg = c_init[crow * Hz + cj];

    for (int t = 0; t < Tz; t++) {
        const __nv_bfloat16* sh = (t == 0) ? h0 : (Hseq + (size_t)(t - 1) * BH);

        // prefetch xg for this thread's 4 mma outputs
        const float* xp = xg + ((size_t)t * Bz + r0) * Gz + jcol;
        float x0 = xp[g0 * Hz];
        float x1 = xp[g1 * Hz];
        float x2 = xp[8 * Gz + g0 * Hz];
        float x3 = xp[8 * Gz + g1 * Hz];

#define STAGE_CHUNK(CK) do {                                               \
        int kc_ = (CK) * 256;                                              \
        _Pragma("unroll")                                                  \
        for (int u = 0; u < 4; u++) {                                      \
            int c_ = tid + 256 * u;                                        \
            int r_ = c_ >> 5, sg_ = c_ & 31;                               \
            cp16(Hsm + r_ * WP + kc_ + sg_ * 8,                            \
                 sh + (size_t)r_ * Hz + kc_ + sg_ * 8);                    \
        }                                                                  \
        CP_COMMIT; } while (0)

        STAGE_CHUNK(0);

        float a0 = 0.f, a1 = 0.f, a2 = 0.f, a3 = 0.f;

#pragma unroll
        for (int ck = 0; ck < 4; ck++) {
            if (ck + 1 < 4) STAGE_CHUNK(ck + 1);
            if (ck + 1 < 4) { CP_WAIT1; } else { CP_WAIT0; }
            __syncthreads();
#pragma unroll
            for (int ki = 0; ki < 16; ki++) {
                const int kk = ck * 16 + ki;
                uint32_t f0, f1, f2, f3;
                uint32_t addr = s2u(Hsm + (mt * 16 + (lane & 15)) * WP + kk * 16 + ((lane >> 4) << 3));
                asm volatile(
                    "ldmatrix.sync.aligned.m8n8.x4.shared.b16 {%0,%1,%2,%3},[%4];"
                    : "=r"(f0), "=r"(f1), "=r"(f2), "=r"(f3) : "r"(addr));
                asm volatile(
                    "mma.sync.aligned.m16n8k16.row.col.f32.bf16.bf16.f32 "
                    "{%0,%1,%2,%3},{%4,%5,%6,%7},{%8,%9},{%0,%1,%2,%3};"
                    : "+f"(a0), "+f"(a1), "+f"(a2), "+f"(a3)
                    : "r"(f0), "r"(f1), "r"(f2), "r"(f3), "r"(wr0[kk]), "r"(wr1[kk]));
            }
        }
#undef STAGE_CHUNK

        // add input gates, exchange with pair lane, compute cell in registers
        a0 += x0; a1 += x1; a2 += x2; a3 += x3;
        float p0 = __shfl_xor_sync(~0u, a0, 1);
        float p1 = __shfl_xor_sync(~0u, a1, 1);
        float p2 = __shfl_xor_sync(~0u, a2, 1);
        float p3 = __shfl_xor_sync(~0u, a3, 1);
        float iv, fv, gv, ov;
        if ((lane & 1) == 0) { iv = a0; fv = a1; gv = p0; ov = p1; }   // row r0
        else                 { iv = p2; fv = p3; gv = a2; ov = a3; }   // row r0+8
        float cn = sigm(fv) * creg + sigm(iv) * tanhf(gv);
        creg = cn;
        float hv = sigm(ov) * tanhf(cn);
        __nv_bfloat16 hb = __float2bfloat16(hv);
        Hseq[(size_t)t * BH + crow * Hz + cj] = hb;
        if (t == Tz - 1) {
            hf[crow * Hz + cj] = hb;
            c_final[crow * Hz + cj] = cn;
        }
        if (t < Tz - 1) gridbar(phase);   // last step ordered by kernel boundary
    }
}

// ---------------- in-place log_softmax (online 2-pass) ------------------------
__global__ __launch_bounds__(256)
void logsoftmax_k(float* __restrict__ out) {
    float* row = out + (size_t)blockIdx.x * Vz;
    float4* r4 = (float4*)row;
    const int tid = threadIdx.x;
    __shared__ float smx[8], ssm[8];

    float m = -1e30f, s = 0.f;
    for (int i = tid; i < Vz / 4; i += 256) {
        float4 v = r4[i];
        float vv[4] = {v.x, v.y, v.z, v.w};
#pragma unroll
        for (int u = 0; u < 4; u++) {
            float val = vv[u];
            if (val <= m) {
                s += __expf(val - m);
            } else {
                s = s * __expf(m - val) + 1.f;
                m = val;
            }
        }
    }
#pragma unroll
    for (int o = 16; o; o >>= 1) {
        float om = __shfl_xor_sync(~0u, m, o);
        float os = __shfl_xor_sync(~0u, s, o);
        float M = fmaxf(m, om);
        s = s * __expf(m - M) + os * __expf(om - M);
        m = M;
    }
    if ((tid & 31) == 0) { smx[tid >> 5] = m; ssm[tid >> 5] = s; }
    __syncthreads();
    if (tid < 32) {
        float mm = (tid < 8) ? smx[tid] : -1e30f;
        float sv = (tid < 8) ? ssm[tid] : 0.f;
#pragma unroll
        for (int o = 4; o; o >>= 1) {
            float om = __shfl_xor_sync(~0u, mm, o);
            float os = __shfl_xor_sync(~0u, sv, o);
            float M = fmaxf(mm, om);
            sv = sv * __expf(mm - M) + os * __expf(om - M);
            mm = M;
        }
        if (tid == 0) { smx[0] = mm; ssm[0] = sv; }
    }
    __syncthreads();
    float lse = smx[0] + logf(ssm[0]);

    for (int i = tid; i < Vz / 4; i += 256) {
        float4 v = r4[i];
        v.x -= lse; v.y -= lse; v.z -= lse; v.w -= lse;
        r4[i] = v;
    }
}

// ---------------- driver ------------------------------------------------------
extern "C" void kernel_launch(void* const* d_in, const int* in_sizes, int n_in,
                              void* d_out, int out_size) {
    const int*   x     = (const int*)d_in[0];
    const int*   tgt   = (const int*)d_in[1];
    const float* emb   = (const float*)d_in[2];
    const float* eWih0 = (const float*)d_in[3];
    const float* eWhh0 = (const float*)d_in[4];
    const float* eb0   = (const float*)d_in[5];
    const float* eWih1 = (const float*)d_in[6];
    const float* eWhh1 = (const float*)d_in[7];
    const float* eb1   = (const float*)d_in[8];
    const float* dWih0 = (const float*)d_in[9];
    const float* dWhh0 = (const float*)d_in[10];
    const float* db0   = (const float*)d_in[11];
    const float* dWih1 = (const float*)d_in[12];
    const float* dWhh1 = (const float*)d_in[13];
    const float* db1   = (const float*)d_in[14];
    const float* fcW   = (const float*)d_in[15];
    const float* fcb   = (const float*)d_in[16];
    float* out = (float*)d_out;

    float *xg, *zc, *cf0, *cf1, *dc;
    __nv_bfloat16 *Wbf, *Whhbf, *Hbf0, *Hbf1, *Abf, *zbf;
    __nv_bfloat16 *hf0, *hf1, *dhf;
    cudaGetSymbolAddress((void**)&xg,    g_xg);
    cudaGetSymbolAddress((void**)&Wbf,   g_Wbf);
    cudaGetSymbolAddress((void**)&Whhbf, g_Whhbf);
    cudaGetSymbolAddress((void**)&Hbf0,  g_Hbf0);
    cudaGetSymbolAddress((void**)&Hbf1,  g_Hbf1);
    cudaGetSymbolAddress((void**)&Abf,   g_Abf);
    cudaGetSymbolAddress((void**)&zbf,   g_zbf);
    cudaGetSymbolAddress((void**)&zc,    g_zc);
    cudaGetSymbolAddress((void**)&hf0,   g_hf0);
    cudaGetSymbolAddress((void**)&hf1,   g_hf1);
    cudaGetSymbolAddress((void**)&cf0,   g_cf0);
    cudaGetSymbolAddress((void**)&cf1,   g_cf1);
    cudaGetSymbolAddress((void**)&dhf,   g_dhf);
    cudaGetSymbolAddress((void**)&dc,    g_dc);

    cudaFuncSetAttribute(lstm_layer, cudaFuncAttributeMaxDynamicSharedMemorySize, LSTM_SMEM);

    dim3 gGate(Gz / 128, TB / 128);
    dim3 gFC(Vz / 128, TB / 128);
    auto cgrid = [](int n) { return (n / 4 + 255) / 256; };

    zero_k<<<BH / 256, 256>>>(zc, BH);
    zero_k<<<(BH / 2) / 256, 256>>>((float*)zbf, BH / 2);

    // ---------- encoder layer 0 ----------
    embed_enc<<<TB, 128>>>(x, emb, Abf);
    f2bf<<<cgrid(Gz * Ez), 256>>>(Wbf, eWih0, Gz * Ez);
    bgemm<0><<<gGate, 256>>>(Abf, Wbf, eb0, xg, TB, Gz, Ez);
    f2bf<<<cgrid(Gz * Hz), 256>>>(Whhbf, eWhh0, Gz * Hz);
    lstm_layer<<<128, 256, LSTM_SMEM>>>(xg, Whhbf, zbf, zc, Hbf0, hf0, cf0);

    // ---------- encoder layer 1 ----------
    f2bf<<<cgrid(Gz * Hz), 256>>>(Wbf, eWih1, Gz * Hz);
    bgemm<0><<<gGate, 256>>>(Hbf0, Wbf, eb1, xg, TB, Gz, Hz);
    f2bf<<<cgrid(Gz * Hz), 256>>>(Whhbf, eWhh1, Gz * Hz);
    lstm_layer<<<128, 256, LSTM_SMEM>>>(xg, Whhbf, zbf, zc, Hbf1, hf1, cf1);

    // ---------- decoder layer 0 (init = enc layer0 finals) ----------
    embed_dec<<<TB, 128>>>(tgt, emb, Abf);
    f2bf<<<cgrid(Gz * Ez), 256>>>(Wbf, dWih0, Gz * Ez);
    bgemm<0><<<gGate, 256>>>(Abf, Wbf, db0, xg, TB, Gz, Ez);
    f2bf<<<cgrid(Gz * Hz), 256>>>(Whhbf, dWhh0, Gz * Hz);
    lstm_layer<<<128, 256, LSTM_SMEM>>>(xg, Whhbf, hf0, cf0, Hbf0, dhf, dc);

    // ---------- decoder layer 1 (init = enc layer1 finals) ----------
    f2bf<<<cgrid(Gz * Hz), 256>>>(Wbf, dWih1, Gz * Hz);
    bgemm<0><<<gGate, 256>>>(Hbf0, Wbf, db1, xg, TB, Gz, Hz);
    f2bf<<<cgrid(Gz * Hz), 256>>>(Whhbf, dWhh1, Gz * Hz);
    lstm_layer<<<128, 256, LSTM_SMEM>>>(xg, Whhbf, hf1, cf1, Hbf1, dhf, dc);

    // ---------- FC projection (fused b,t remap) + log_softmax ----------
    f2bf<<<cgrid(Vz * Hz), 256>>>(Wbf, fcW, Vz * Hz);
    bgemm<1><<<gFC, 256>>>(Hbf1, Wbf, fcb, out, TB, Vz, Hz);
    logsoftmax_k<<<TB, 256>>>(out);
}